// round 13
// baseline (speedup 1.0000x reference)
#include <cuda_runtime.h>
#include <math.h>
#include <stdint.h>

#define NN 768
#define HH 12
#define CS 384
#define PROJ_N 1152
#define FEAT_N 2112   // [o 192 | ptx 96 | pty 96 | ptz 96 | ptnorm 96 | opair 1536]

typedef unsigned long long ull;

#define S1 0.14433756729740643f      // sqrt(1/48)
#define SQ13 0.5773502691896258f     // sqrt(1/3)
#define HWF 0.13608276348795434f     // sqrt(1/54)

__device__ __forceinline__ void ffma2(ull& d, ull a, ull b) {
    asm("fma.rn.f32x2 %0, %1, %2, %0;" : "+l"(d) : "l"(a), "l"(b));
}
__device__ __forceinline__ ull pack2(float x, float y) {
    ull r; asm("mov.b64 %0, {%1, %2};" : "=l"(r) : "f"(x), "f"(y)); return r;
}
__device__ __forceinline__ float2 unpack2(ull v) {
    float2 r; asm("mov.b64 {%0, %1}, %2;" : "=f"(r.x), "=f"(r.y) : "l"(v)); return r;
}
__device__ __forceinline__ uint32_t to_tf32(float f) {
    uint32_t r; asm("cvt.rna.tf32.f32 %0, %1;" : "=r"(r) : "f"(f)); return r;
}
__device__ __forceinline__ void mma_tf32(float c[4],
    uint32_t a0, uint32_t a1, uint32_t a2, uint32_t a3,
    uint32_t b0, uint32_t b1)
{
    asm("mma.sync.aligned.m16n8k8.row.col.f32.tf32.tf32.f32 "
        "{%0,%1,%2,%3}, {%4,%5,%6,%7}, {%8,%9}, {%0,%1,%2,%3};"
        : "+f"(c[0]), "+f"(c[1]), "+f"(c[2]), "+f"(c[3])
        : "r"(a0), "r"(a1), "r"(a2), "r"(a3), "r"(b0), "r"(b1));
}

// ---------------- scratch ----------------
__device__ float g_proj[NN * PROJ_N];
__device__ float g_v[NN * 192];
__device__ float g_vpts[NN * 288];
__device__ float g_qb[HH * NN * 32];
__device__ float g_kb[HH * NN * 32];
__device__ float g_qkp[(size_t)NN * HH * NN]; // [i][h][j]
__device__ float g_bias[(size_t)NN * NN * HH];// [i][j][h]
__device__ float g_a[(size_t)NN * HH * NN];   // [i][h][j]
__device__ float g_aT[(size_t)NN * NN * HH];  // [i][j][h]
__device__ float g_optg[NN * 288];
__device__ float g_feats[NN * FEAT_N];

// ---------------- GEMM via 3xTF32 MMA: out = A @ W + bias, segmented over N ----------------
// BM=64, BN=64, BK=16, 256 thr (8 warps: 4m x 2n), fp32-grade precision via hi/lo split.
#define APITCH 20
#define BPITCH 72
__global__ __launch_bounds__(256) void gemm_mma_kernel(
    const float* __restrict__ A, int K,
    const float* __restrict__ w0, const float* __restrict__ w1,
    const float* __restrict__ w2, const float* __restrict__ w3,
    const float* __restrict__ b0, const float* __restrict__ b1,
    const float* __restrict__ b2, const float* __restrict__ b3,
    int e0, int e1, int e2, int e3,
    float* __restrict__ out, int ldo)
{
    __shared__ uint32_t Ah[64 * APITCH], Al[64 * APITCH];
    __shared__ uint32_t Bh[16 * BPITCH], Bl[16 * BPITCH];

    const int m0 = blockIdx.y * 64;
    const int n0 = blockIdx.x * 64;
    const int t = threadIdx.x;
    const int warp = t >> 5, lane = t & 31;
    const int wm = warp & 3, wn = warp >> 2;
    const int tg = lane & 3, gp = lane >> 2;

    // B loader mapping: col quad (boundaries are multiples of 4)
    const int brow = t >> 4;
    const int bn = (t & 15) * 4;
    const int ncol = n0 + bn;
    const float* W; const float* bias; int base, segN;
    if (ncol < e0)      { W = w0; bias = b0; base = 0;  segN = e0; }
    else if (ncol < e1) { W = w1; bias = b1; base = e0; segN = e1 - e0; }
    else if (ncol < e2) { W = w2; bias = b2; base = e1; segN = e2 - e1; }
    else                { W = w3; bias = b3; base = e2; segN = e3 - e2; }

    // A loader mapping
    const int ar = t >> 2, ak = (t & 3) * 4;

    float acc[4][4] = {};   // [ntile][c0..c3]

    for (int k0 = 0; k0 < K; k0 += 16) {
        __syncthreads();
        // stage A hi/lo (pitch 20, uint4 aligned)
        {
            float4 v = *(const float4*)&A[(size_t)(m0 + ar) * K + k0 + ak];
            uint4 hi, lo;
            hi.x = to_tf32(v.x); lo.x = to_tf32(v.x - __uint_as_float(hi.x));
            hi.y = to_tf32(v.y); lo.y = to_tf32(v.y - __uint_as_float(hi.y));
            hi.z = to_tf32(v.z); lo.z = to_tf32(v.z - __uint_as_float(hi.z));
            hi.w = to_tf32(v.w); lo.w = to_tf32(v.w - __uint_as_float(hi.w));
            *(uint4*)&Ah[ar * APITCH + ak] = hi;
            *(uint4*)&Al[ar * APITCH + ak] = lo;
        }
        // stage B hi/lo (pitch 72, uint4 aligned)
        {
            float4 v = *(const float4*)&W[(size_t)(k0 + brow) * segN + (ncol - base)];
            uint4 hi, lo;
            hi.x = to_tf32(v.x); lo.x = to_tf32(v.x - __uint_as_float(hi.x));
            hi.y = to_tf32(v.y); lo.y = to_tf32(v.y - __uint_as_float(hi.y));
            hi.z = to_tf32(v.z); lo.z = to_tf32(v.z - __uint_as_float(hi.z));
            hi.w = to_tf32(v.w); lo.w = to_tf32(v.w - __uint_as_float(hi.w));
            *(uint4*)&Bh[brow * BPITCH + bn] = hi;
            *(uint4*)&Bl[brow * BPITCH + bn] = lo;
        }
        __syncthreads();

        #pragma unroll
        for (int kk = 0; kk < 2; kk++) {
            const int k8 = kk * 8;
            const int ra = (wm * 16 + gp) * APITCH + k8 + tg;
            const int rb = (wm * 16 + gp + 8) * APITCH + k8 + tg;
            uint32_t a0h = Ah[ra],     a1h = Ah[rb];
            uint32_t a2h = Ah[ra + 4], a3h = Ah[rb + 4];
            uint32_t a0l = Al[ra],     a1l = Al[rb];
            uint32_t a2l = Al[ra + 4], a3l = Al[rb + 4];
            #pragma unroll
            for (int nt = 0; nt < 4; nt++) {
                const int nb = wn * 32 + nt * 8 + gp;
                const int i1 = (k8 + tg) * BPITCH + nb;
                const int i2 = (k8 + tg + 4) * BPITCH + nb;
                uint32_t bh0 = Bh[i1], bh1 = Bh[i2];
                uint32_t bl0 = Bl[i1], bl1 = Bl[i2];
                mma_tf32(acc[nt], a0h, a1h, a2h, a3h, bh0, bh1);
                mma_tf32(acc[nt], a0l, a1l, a2l, a3l, bh0, bh1);
                mma_tf32(acc[nt], a0h, a1h, a2h, a3h, bl0, bl1);
            }
        }
    }

    // epilogue
    const int r0 = m0 + wm * 16 + gp;
    const int r1 = r0 + 8;
    #pragma unroll
    for (int nt = 0; nt < 4; nt++) {
        const int col = n0 + wn * 32 + nt * 8 + 2 * tg;
        const float* bp; int bb;
        if (col < e0)      { bp = b0; bb = 0; }
        else if (col < e1) { bp = b1; bb = e0; }
        else if (col < e2) { bp = b2; bb = e1; }
        else               { bp = b3; bb = e2; }
        float2 bv = *(const float2*)&bp[col - bb];
        float2 o0, o1;
        o0.x = acc[nt][0] + bv.x; o0.y = acc[nt][1] + bv.y;
        o1.x = acc[nt][2] + bv.x; o1.y = acc[nt][3] + bv.y;
        *(float2*)&out[(size_t)r0 * ldo + col] = o0;
        *(float2*)&out[(size_t)r1 * ldo + col] = o1;
    }
}

// ---------------- prep ----------------
__global__ __launch_bounds__(384) void prep_kernel(
    const float* __restrict__ rot, const float* __restrict__ trans,
    const float* __restrict__ head_w)
{
    __shared__ float s_qp3[144];
    __shared__ float s_kp3[144];

    const int n = blockIdx.x;
    const int t = threadIdx.x;
    const float* pr = &g_proj[(size_t)n * PROJ_N];

    if (t < 192) {
        int h = t >> 4, c = t & 15;
        g_kb[((size_t)h * NN + n) * 32 + c] = pr[192 + h * 32 + c];
        g_v[n * 192 + t] = pr[192 + h * 32 + 16 + c];
    }
    float r[9], tr[3];
    #pragma unroll
    for (int e = 0; e < 9; e++) r[e] = rot[n * 9 + e];
    tr[0] = trans[n * 3 + 0]; tr[1] = trans[n * 3 + 1]; tr[2] = trans[n * 3 + 2];

    if (t < 48) {
        float p0 = pr[576 + 0 * 48 + t];
        float p1 = pr[576 + 1 * 48 + t];
        float p2 = pr[576 + 2 * 48 + t];
        #pragma unroll
        for (int ii = 0; ii < 3; ii++)
            s_qp3[t * 3 + ii] = r[ii * 3 + 0] * p0 + r[ii * 3 + 1] * p1 + r[ii * 3 + 2] * p2 + tr[ii];
    }
    if (t >= 64 && t < 208) {
        int u = t - 64;
        float p0 = pr[720 + 0 * 144 + u];
        float p1 = pr[720 + 1 * 144 + u];
        float p2 = pr[720 + 2 * 144 + u];
        int h = u / 12, p = u % 12;
        #pragma unroll
        for (int ii = 0; ii < 3; ii++) {
            float o = r[ii * 3 + 0] * p0 + r[ii * 3 + 1] * p1 + r[ii * 3 + 2] * p2 + tr[ii];
            if (p < 4) s_kp3[(h * 4 + p) * 3 + ii] = o;
            else       g_vpts[n * 288 + (h * 8 + (p - 4)) * 3 + ii] = o;
        }
    }
    __syncthreads();

    {
        int h = t >> 5, e = t & 31;
        float x = head_w[h];
        float hw = ((x > 20.f) ? x : log1pf(__expf(x))) * HWF;

        float qv;
        if (e < 16)       qv = pr[h * 16 + e] * S1;
        else if (e < 28)  qv = s_qp3[h * 12 + (e - 16)] * hw;
        else if (e == 28) qv = -0.5f * hw;
        else if (e == 29) {
            float nq = 0.f;
            #pragma unroll
            for (int d = 0; d < 12; d++) { float v = s_qp3[h * 12 + d]; nq += v * v; }
            qv = -0.5f * hw * nq;
        } else qv = 0.f;
        g_qb[((size_t)h * NN + n) * 32 + e] = qv;

        if (e >= 16) {
            float kv2;
            if (e < 28)       kv2 = s_kp3[h * 12 + (e - 16)];
            else if (e == 28) {
                float nk = 0.f;
                #pragma unroll
                for (int d = 0; d < 12; d++) { float v = s_kp3[h * 12 + d]; nk += v * v; }
                kv2 = nk;
            }
            else if (e == 29) kv2 = 1.f;
            else              kv2 = 0.f;
            g_kb[((size_t)h * NN + n) * 32 + e] = kv2;
        }
    }
}

// ---------------- qkpts ----------------
__global__ __launch_bounds__(256) void qkpts_kernel(const float* __restrict__ mask)
{
    __shared__ float As[32][68];
    __shared__ float Bs[32][68];
    __shared__ float s_mi[64], s_mj[64];

    const int i0 = blockIdx.x * 64;
    const int j0 = blockIdx.y * 64;
    const int h  = blockIdx.z;
    const int t = threadIdx.x;

    #pragma unroll
    for (int r2 = 0; r2 < 2; r2++) {
        int li = t + r2 * 256;
        int row = li >> 3, c4 = (li & 7) * 4;
        float4 a = *(const float4*)&g_qb[((size_t)h * NN + i0 + row) * 32 + c4];
        As[c4 + 0][row] = a.x; As[c4 + 1][row] = a.y;
        As[c4 + 2][row] = a.z; As[c4 + 3][row] = a.w;
        float4 b = *(const float4*)&g_kb[((size_t)h * NN + j0 + row) * 32 + c4];
        Bs[c4 + 0][row] = b.x; Bs[c4 + 1][row] = b.y;
        Bs[c4 + 2][row] = b.z; Bs[c4 + 3][row] = b.w;
    }
    if (t < 64)              s_mi[t] = mask[i0 + t];
    else if (t < 128)        s_mj[t - 64] = mask[j0 + t - 64];
    __syncthreads();

    const int ty = t >> 4, tx = t & 15;
    float acc[4][4] = {};
    #pragma unroll
    for (int k = 0; k < 32; k++) {
        float4 a4 = *(const float4*)&As[k][ty * 4];
        float4 b4 = *(const float4*)&Bs[k][tx * 4];
        acc[0][0] += a4.x * b4.x; acc[0][1] += a4.x * b4.y; acc[0][2] += a4.x * b4.z; acc[0][3] += a4.x * b4.w;
        acc[1][0] += a4.y * b4.x; acc[1][1] += a4.y * b4.y; acc[1][2] += a4.y * b4.z; acc[1][3] += a4.y * b4.w;
        acc[2][0] += a4.z * b4.x; acc[2][1] += a4.z * b4.y; acc[2][2] += a4.z * b4.z; acc[2][3] += a4.z * b4.w;
        acc[3][0] += a4.w * b4.x; acc[3][1] += a4.w * b4.y; acc[3][2] += a4.w * b4.z; acc[3][3] += a4.w * b4.w;
    }
    #pragma unroll
    for (int rr = 0; rr < 4; rr++) {
        float mi = s_mi[ty * 4 + rr];
        float4 o;
        o.x = acc[rr][0] + 100000.f * (mi * s_mj[tx * 4 + 0] - 1.f);
        o.y = acc[rr][1] + 100000.f * (mi * s_mj[tx * 4 + 1] - 1.f);
        o.z = acc[rr][2] + 100000.f * (mi * s_mj[tx * 4 + 2] - 1.f);
        o.w = acc[rr][3] + 100000.f * (mi * s_mj[tx * 4 + 3] - 1.f);
        *(float4*)&g_qkp[(size_t)(i0 + ty * 4 + rr) * 9216 + h * 768 + j0 + tx * 4] = o;
    }
}

// ---------------- bias v2: smem-staged tf32 MMA GEMM [589824 x 128] @ [128 x 12] ----------------
#define BT_TILES (NN * NN / 128)          // 4608
#define BS_SMEM_BYTES (128 * 132 * 4)     // 67584
__global__ __launch_bounds__(256, 2) void bias_kernel(
    const float* __restrict__ z, const float* __restrict__ w_b,
    const float* __restrict__ b_b)
{
    extern __shared__ uint32_t s_z[];     // [128][132] tf32 bits

    const int t = threadIdx.x;
    const int w = t >> 5;
    const int lane = t & 31;
    const int tg = lane & 3;
    const int gp = lane >> 2;

    uint32_t B0[16][2], B1[16][2];
    #pragma unroll
    for (int kk = 0; kk < 16; kk++) {
        int k0 = kk * 8 + tg, k1 = k0 + 4;
        B0[kk][0] = to_tf32(w_b[k0 * 12 + gp]);
        B0[kk][1] = to_tf32(w_b[k1 * 12 + gp]);
        float w10 = (gp < 4) ? w_b[k0 * 12 + 8 + gp] : 0.f;
        float w11 = (gp < 4) ? w_b[k1 * 12 + 8 + gp] : 0.f;
        B1[kk][0] = to_tf32(w10);
        B1[kk][1] = to_tf32(w11);
    }
    const int cb = 2 * tg;
    const float bb0 = b_b[cb], bb1 = b_b[cb + 1];
    const float bb8 = (cb < 4) ? b_b[8 + cb] : 0.f;
    const float bb9 = (cb < 4) ? b_b[9 + cb] : 0.f;

    const int col4 = lane * 4;
    const int rowg = w;

    for (int tile = blockIdx.x; tile < BT_TILES; tile += gridDim.x) {
        const float* zt = z + (size_t)tile * 128 * 128;
        __syncthreads();
        #pragma unroll
        for (int k = 0; k < 16; k++) {
            int row = rowg + k * 8;
            float4 v = __ldg((const float4*)(zt + row * 128 + col4));
            uint4 u;
            u.x = to_tf32(v.x); u.y = to_tf32(v.y);
            u.z = to_tf32(v.z); u.w = to_tf32(v.w);
            *(uint4*)&s_z[row * 132 + col4] = u;
        }
        __syncthreads();

        const uint32_t* sw = s_z + (w * 16) * 132;
        float c0[4] = {0.f, 0.f, 0.f, 0.f};
        float c1[4] = {0.f, 0.f, 0.f, 0.f};
        #pragma unroll
        for (int kk = 0; kk < 16; kk++) {
            int co = kk * 8 + tg;
            uint32_t a0 = sw[gp * 132 + co];
            uint32_t a1 = sw[(gp + 8) * 132 + co];
            uint32_t a2 = sw[gp * 132 + co + 4];
            uint32_t a3 = sw[(gp + 8) * 132 + co + 4];
            mma_tf32(c0, a0, a1, a2, a3, B0[kk][0], B0[kk][1]);
            mma_tf32(c1, a0, a1, a2, a3, B1[kk][0], B1[kk][1]);
        }

        float* outr = g_bias + ((size_t)tile * 128 + w * 16) * 12;
        {
            float2 o;
            o.x = SQ13 * (c0[0] + bb0); o.y = SQ13 * (c0[1] + bb1);
            *(float2*)&outr[gp * 12 + cb] = o;
            o.x = SQ13 * (c0[2] + bb0); o.y = SQ13 * (c0[3] + bb1);
            *(float2*)&outr[(gp + 8) * 12 + cb] = o;
        }
        if (cb < 4) {
            float2 o;
            o.x = SQ13 * (c1[0] + bb8); o.y = SQ13 * (c1[1] + bb9);
            *(float2*)&outr[gp * 12 + 8 + cb] = o;
            o.x = SQ13 * (c1[2] + bb8); o.y = SQ13 * (c1[3] + bb9);
            *(float2*)&outr[(gp + 8) * 12 + 8 + cb] = o;
        }
    }
}

// ---------------- softmax: logits = qkp + bias; softmax per head; write a / aT ----------------
#define LP 772
__global__ __launch_bounds__(256) void softmax_kernel(const float* __restrict__ ss)
{
    __shared__ float s_l[12 * LP];
    __shared__ float s_w[768];

    const int i = blockIdx.x;
    const int t = threadIdx.x;

    for (int idx = t; idx < 9216; idx += 256) {
        int j = idx / 12, h = idx - j * 12;
        s_l[h * LP + j] = g_bias[(size_t)i * 9216 + idx];
    }
    for (int idx = t; idx < 768; idx += 256)
        s_w[idx] = __expf(ss[(size_t)i * 768 + idx]) - 0.99f;
    __syncthreads();
    for (int idx = t; idx < 9216; idx += 256) {
        int h = idx / 768, j = idx - h * 768;
        s_l[h * LP + j] += g_qkp[(size_t)i * 9216 + idx];
    }
    __syncthreads();

    const int wrp = t >> 5, lane = t & 31;
    for (int h = wrp; h < 12; h += 8) {
        float* lr = &s_l[h * LP];
        float m = -1e30f;
        for (int j = lane; j < 768; j += 32) m = fmaxf(m, lr[j]);
        #pragma unroll
        for (int o = 16; o; o >>= 1) m = fmaxf(m, __shfl_xor_sync(0xffffffffu, m, o));
        float sum = 0.f;
        for (int j = lane; j < 768; j += 32) {
            float p = __expf(lr[j] - m) * s_w[j];
            lr[j] = p;
            sum += p;
        }
        #pragma unroll
        for (int o = 16; o; o >>= 1) sum += __shfl_xor_sync(0xffffffffu, sum, o);
        float inv = 1.f / sum;
        for (int j = lane; j < 768; j += 32) lr[j] *= inv;
    }
    __syncthreads();

    for (int idx = t; idx < 9216; idx += 256) {
        int h = idx / 768, j = idx - h * 768;
        g_a[(size_t)i * 9216 + idx] = s_l[h * LP + j];
    }
    for (int idx = t; idx < 9216; idx += 256) {
        int j = idx / 12, h = idx - j * 12;
        g_aT[(size_t)i * 9216 + idx] = s_l[h * LP + j];
    }
}

// ---------------- opair: o_pair[i][h][c] = sum_j a[i][j][h]*z[i][j][c] ----------------
#define OP_SMEM_FLOATS (8 * 12 * 128)
__global__ __launch_bounds__(256) void opair_kernel(const float* __restrict__ z)
{
    extern __shared__ float s_part[];   // [w][12][128]

    const int i = blockIdx.x;
    const int t = threadIdx.x;
    const int w = t >> 5, lane = t & 31;

    ull acc[6][4];
    #pragma unroll
    for (int q = 0; q < 6; q++)
        #pragma unroll
        for (int c = 0; c < 4; c++) acc[q][c] = 0ull;

    const float* zb = z + (size_t)i * 768 * 128 + lane * 4;
    const float* ab = g_aT + (size_t)i * 9216;

    for (int jb = w * 4; jb < 768; jb += 32) {
        float4 zv[4];
        float4 av[4][3];
        #pragma unroll
        for (int u = 0; u < 4; u++) {
            zv[u] = __ldg((const float4*)(zb + (size_t)(jb + u) * 128));
            av[u][0] = __ldg((const float4*)(ab + (jb + u) * 12));
            av[u][1] = __ldg((const float4*)(ab + (jb + u) * 12 + 4));
            av[u][2] = __ldg((const float4*)(ab + (jb + u) * 12 + 8));
        }
        #pragma unroll
        for (int u = 0; u < 4; u++) {
            ull ap[6];
            ap[0] = pack2(av[u][0].x, av[u][0].y);
            ap[1] = pack2(av[u][0].z, av[u][0].w);
            ap[2] = pack2(av[u][1].x, av[u][1].y);
            ap[3] = pack2(av[u][1].z, av[u][1].w);
            ap[4] = pack2(av[u][2].x, av[u][2].y);
            ap[5] = pack2(av[u][2].z, av[u][2].w);
            float zc[4] = {zv[u].x, zv[u].y, zv[u].z, zv[u].w};
            #pragma unroll
            for (int c = 0; c < 4; c++) {
                ull zz = pack2(zc[c], zc[c]);
                #pragma unroll
                for (int q = 0; q < 6; q++)
                    ffma2(acc[q][c], ap[q], zz);
            }
        }
    }

    #pragma unroll
    for (int q = 0; q < 6; q++) {
        #pragma unroll
        for (int c = 0; c < 4; c++) {
            float2 u = unpack2(acc[q][c]);
            s_part[(w * 12 + 2 * q + 0) * 128 + lane * 4 + c] = u.x;
            s_part[(w * 12 + 2 * q + 1) * 128 + lane * 4 + c] = u.y;
        }
    }
    __syncthreads();

    for (int idx = t; idx < 1536; idx += 256) {
        int h = idx >> 7, c = idx & 127;
        float s = 0.f;
        #pragma unroll
        for (int ww = 0; ww < 8; ww++)
            s += s_part[(ww * 12 + h) * 128 + c];
        g_feats[(size_t)i * FEAT_N + 576 + h * 128 + c] = s;
    }
}

// ---------------- ov: 32-row tiles, 128 threads, grid (24,12); s_a pitch 68 ----------------
__global__ __launch_bounds__(128) void ov_kernel()
{
    __shared__ float s_a[32 * 68];
    __shared__ float s_v[64 * 40];

    const int i0 = blockIdx.x * 32;
    const int h  = blockIdx.y;
    const int t = threadIdx.x;
    const int ig = t >> 3;
    const int og = t & 7;

    float acc[2][5] = {};

    for (int j0 = 0; j0 < 768; j0 += 64) {
        #pragma unroll
        for (int it = 0; it < 4; it++) {
            int idx = t + it * 128;
            int row = idx >> 4, q = idx & 15;
            float4 av = *(const float4*)&g_a[((size_t)(i0 + row) * 12 + h) * 768 + j0 + q * 4];
            *(float4*)&s_a[row * 68 + q * 4] = av;
        }
        #pragma unroll
        for (int it = 0; it < 5; it++) {
            int idx = t + it * 128;
            int jj = idx / 10, q = idx - jj * 10;
            float4 vv = (q < 4)
                ? *(const float4*)&g_v[(j0 + jj) * 192 + h * 16 + q * 4]
                : *(const float4*)&g_vpts[(j0 + jj) * 288 + h * 24 + (q - 4) * 4];
            *(float4*)&s_v[jj * 40 + q * 4] = vv;
        }
        __syncthreads();
        #pragma unroll 8
        for (int jj = 0; jj < 64; jj++) {
            float a0 = s_a[(ig * 2 + 0) * 68 + jj];
            float a1 = s_a[(ig * 2 + 1) * 68 + jj];
            const float* vp = &s_v[jj * 40 + og * 5];
            #pragma unroll
            for (int u = 0; u < 5; u++) {
                float vv = vp[u];
                acc[0][u] += a0 * vv;
                acc[1][u] += a1 * vv;
            }
        }
        __syncthreads();
    }
    #pragma unroll
    for (int r = 0; r < 2; r++) {
        int n = i0 + ig * 2 + r;
        #pragma unroll
        for (int u = 0; u < 5; u++) {
            int e = og * 5 + u;
            if (e < 16) g_feats[(size_t)n * FEAT_N + h * 16 + e] = acc[r][u];
            else        g_optg[n * 288 + h * 24 + (e - 16)] = acc[r][u];
        }
    }
}

// ---------------- optfinal ----------------
__global__ __launch_bounds__(96) void optfinal_kernel(
    const float* __restrict__ rot, const float* __restrict__ trans)
{
    const int n = blockIdx.x;
    const int hp = threadIdx.x;
    float r[9], tr[3];
    #pragma unroll
    for (int e = 0; e < 9; e++) r[e] = rot[n * 9 + e];
    tr[0] = trans[n * 3 + 0]; tr[1] = trans[n * 3 + 1]; tr[2] = trans[n * 3 + 2];

    float gx = g_optg[n * 288 + hp * 3 + 0] - tr[0];
    float gy = g_optg[n * 288 + hp * 3 + 1] - tr[1];
    float gz = g_optg[n * 288 + hp * 3 + 2] - tr[2];
    float l0 = r[0] * gx + r[3] * gy + r[6] * gz;
    float l1 = r[1] * gx + r[4] * gy + r[7] * gz;
    float l2 = r[2] * gx + r[5] * gy + r[8] * gz;

    float* f = &g_feats[(size_t)n * FEAT_N];
    f[192 + hp] = l0;
    f[288 + hp] = l1;
    f[384 + hp] = l2;
    f[480 + hp] = sqrtf(l0 * l0 + l1 * l1 + l2 * l2 + 1e-8f);
}

// ---------------- launch ----------------
extern "C" void kernel_launch(void* const* d_in, const int* in_sizes, int n_in,
                              void* d_out, int out_size)
{
    const float* s       = (const float*)d_in[0];
    const float* z       = (const float*)d_in[1];
    const float* rot     = (const float*)d_in[2];
    const float* trans   = (const float*)d_in[3];
    const float* mask    = (const float*)d_in[4];
    const float* ss      = (const float*)d_in[5];
    const float* w_q     = (const float*)d_in[6];
    const float* b_q     = (const float*)d_in[7];
    const float* w_kv    = (const float*)d_in[8];
    const float* b_kv    = (const float*)d_in[9];
    const float* w_qp    = (const float*)d_in[10];
    const float* b_qp    = (const float*)d_in[11];
    const float* w_kvp   = (const float*)d_in[12];
    const float* b_kvp   = (const float*)d_in[13];
    const float* w_b     = (const float*)d_in[14];
    const float* b_b     = (const float*)d_in[15];
    const float* head_w  = (const float*)d_in[16];
    const float* w_out   = (const float*)d_in[17];
    const float* b_out   = (const float*)d_in[18];
    float* out = (float*)d_out;

    float* proj;  cudaGetSymbolAddress((void**)&proj, g_proj);
    float* feats; cudaGetSymbolAddress((void**)&feats, g_feats);

    static bool attr_done = false;
    if (!attr_done) {
        cudaFuncSetAttribute(opair_kernel,
                             cudaFuncAttributeMaxDynamicSharedMemorySize,
                             OP_SMEM_FLOATS * 4);
        cudaFuncSetAttribute(bias_kernel,
                             cudaFuncAttributeMaxDynamicSharedMemorySize,
                             BS_SMEM_BYTES);
        attr_done = true;
    }

    // K1: projections (768 x 1152) via 3xTF32 MMA
    gemm_mma_kernel<<<dim3(18, 12), 256>>>(
        s, CS, w_q, w_kv, w_qp, w_kvp, b_q, b_kv, b_qp, b_kvp,
        192, 576, 720, 1152, proj, PROJ_N);

    // K2: split k/v, rotate points, build logit-GEMM rows
    prep_kernel<<<NN, 384>>>(rot, trans, head_w);

    // K2b: qk+pts+mask logits as 30-dim GEMM
    qkpts_kernel<<<dim3(12, 12, 12), 256>>>(mask);

    // K3a: z-bias via smem-staged tf32 MMA (z pass 1)
    bias_kernel<<<296, 256, BS_SMEM_BYTES>>>(z, w_b, b_b);

    // K3b: softmax
    softmax_kernel<<<NN, 256>>>(ss);

    // K3c: o_pair (z pass 2)
    opair_kernel<<<NN, 256, OP_SMEM_FLOATS * 4>>>(z);

    // K4: o and o_pt accumulation
    ov_kernel<<<dim3(24, 12), 128>>>();

    // K5: finalize o_pt + norms
    optfinal_kernel<<<NN, 96>>>(rot, trans);

    // K6: output GEMM (768 x 384, K=2112) via 3xTF32 MMA
    gemm_mma_kernel<<<dim3(6, 12), 256>>>(
        feats, FEAT_N, w_out, w_out, w_out, w_out, b_out, b_out, b_out, b_out,
        384, 384, 384, 384, out, CS);
}

// round 14
// speedup vs baseline: 1.0130x; 1.0130x over previous
#include <cuda_runtime.h>
#include <math.h>
#include <stdint.h>

#define NN 768
#define HH 12
#define CS 384
#define PROJ_N 1152
#define FEAT_N 2112   // [o 192 | ptx 96 | pty 96 | ptz 96 | ptnorm 96 | opair 1536]

typedef unsigned long long ull;

#define S1 0.14433756729740643f      // sqrt(1/48)
#define SQ13 0.5773502691896258f     // sqrt(1/3)
#define HWF 0.13608276348795434f     // sqrt(1/54)

__device__ __forceinline__ void ffma2(ull& d, ull a, ull b) {
    asm("fma.rn.f32x2 %0, %1, %2, %0;" : "+l"(d) : "l"(a), "l"(b));
}
__device__ __forceinline__ ull pack2(float x, float y) {
    ull r; asm("mov.b64 %0, {%1, %2};" : "=l"(r) : "f"(x), "f"(y)); return r;
}
__device__ __forceinline__ float2 unpack2(ull v) {
    float2 r; asm("mov.b64 {%0, %1}, %2;" : "=f"(r.x), "=f"(r.y) : "l"(v)); return r;
}
__device__ __forceinline__ uint32_t to_tf32(float f) {
    uint32_t r; asm("cvt.rna.tf32.f32 %0, %1;" : "=r"(r) : "f"(f)); return r;
}
__device__ __forceinline__ void mma_tf32(float c[4],
    uint32_t a0, uint32_t a1, uint32_t a2, uint32_t a3,
    uint32_t b0, uint32_t b1)
{
    asm("mma.sync.aligned.m16n8k8.row.col.f32.tf32.tf32.f32 "
        "{%0,%1,%2,%3}, {%4,%5,%6,%7}, {%8,%9}, {%0,%1,%2,%3};"
        : "+f"(c[0]), "+f"(c[1]), "+f"(c[2]), "+f"(c[3])
        : "r"(a0), "r"(a1), "r"(a2), "r"(a3), "r"(b0), "r"(b1));
}

// ---------------- scratch ----------------
__device__ float g_proj[NN * PROJ_N];
__device__ float g_v[NN * 192];
__device__ float g_vpts[NN * 288];
__device__ float g_qb[HH * NN * 32];
__device__ float g_kb[HH * NN * 32];
__device__ float g_qkp[(size_t)NN * HH * NN]; // [i][h][j]
__device__ float g_bias[(size_t)NN * NN * HH];// [i][j][h]
__device__ float g_a[(size_t)NN * HH * NN];   // [i][h][j]
__device__ float g_aT[(size_t)NN * NN * HH];  // [i][j][h]
__device__ float g_optg[NN * 288];
__device__ float g_feats[NN * FEAT_N];

// ---------------- GEMM via 3xTF32 MMA: out = A @ W + bias, segmented over N ----------------
// BM=64, BN=64, BK=16, 256 thr (8 warps: 4m x 2n), fp32-grade precision via hi/lo split.
#define APITCH 20
#define BPITCH 72
__global__ __launch_bounds__(256) void gemm_mma_kernel(
    const float* __restrict__ A, int K,
    const float* __restrict__ w0, const float* __restrict__ w1,
    const float* __restrict__ w2, const float* __restrict__ w3,
    const float* __restrict__ b0, const float* __restrict__ b1,
    const float* __restrict__ b2, const float* __restrict__ b3,
    int e0, int e1, int e2, int e3,
    float* __restrict__ out, int ldo)
{
    __shared__ uint32_t Ah[64 * APITCH], Al[64 * APITCH];
    __shared__ uint32_t Bh[16 * BPITCH], Bl[16 * BPITCH];

    const int m0 = blockIdx.y * 64;
    const int n0 = blockIdx.x * 64;
    const int t = threadIdx.x;
    const int warp = t >> 5, lane = t & 31;
    const int wm = warp & 3, wn = warp >> 2;
    const int tg = lane & 3, gp = lane >> 2;

    // B loader mapping: col quad (boundaries are multiples of 4)
    const int brow = t >> 4;
    const int bn = (t & 15) * 4;
    const int ncol = n0 + bn;
    const float* W; const float* bias; int base, segN;
    if (ncol < e0)      { W = w0; bias = b0; base = 0;  segN = e0; }
    else if (ncol < e1) { W = w1; bias = b1; base = e0; segN = e1 - e0; }
    else if (ncol < e2) { W = w2; bias = b2; base = e1; segN = e2 - e1; }
    else                { W = w3; bias = b3; base = e2; segN = e3 - e2; }

    // A loader mapping
    const int ar = t >> 2, ak = (t & 3) * 4;

    float acc[4][4] = {};   // [ntile][c0..c3]

    for (int k0 = 0; k0 < K; k0 += 16) {
        __syncthreads();
        // stage A hi/lo (pitch 20, uint4 aligned)
        {
            float4 v = *(const float4*)&A[(size_t)(m0 + ar) * K + k0 + ak];
            uint4 hi, lo;
            hi.x = to_tf32(v.x); lo.x = to_tf32(v.x - __uint_as_float(hi.x));
            hi.y = to_tf32(v.y); lo.y = to_tf32(v.y - __uint_as_float(hi.y));
            hi.z = to_tf32(v.z); lo.z = to_tf32(v.z - __uint_as_float(hi.z));
            hi.w = to_tf32(v.w); lo.w = to_tf32(v.w - __uint_as_float(hi.w));
            *(uint4*)&Ah[ar * APITCH + ak] = hi;
            *(uint4*)&Al[ar * APITCH + ak] = lo;
        }
        // stage B hi/lo (pitch 72, uint4 aligned)
        {
            float4 v = *(const float4*)&W[(size_t)(k0 + brow) * segN + (ncol - base)];
            uint4 hi, lo;
            hi.x = to_tf32(v.x); lo.x = to_tf32(v.x - __uint_as_float(hi.x));
            hi.y = to_tf32(v.y); lo.y = to_tf32(v.y - __uint_as_float(hi.y));
            hi.z = to_tf32(v.z); lo.z = to_tf32(v.z - __uint_as_float(hi.z));
            hi.w = to_tf32(v.w); lo.w = to_tf32(v.w - __uint_as_float(hi.w));
            *(uint4*)&Bh[brow * BPITCH + bn] = hi;
            *(uint4*)&Bl[brow * BPITCH + bn] = lo;
        }
        __syncthreads();

        #pragma unroll
        for (int kk = 0; kk < 2; kk++) {
            const int k8 = kk * 8;
            const int ra = (wm * 16 + gp) * APITCH + k8 + tg;
            const int rb = (wm * 16 + gp + 8) * APITCH + k8 + tg;
            uint32_t a0h = Ah[ra],     a1h = Ah[rb];
            uint32_t a2h = Ah[ra + 4], a3h = Ah[rb + 4];
            uint32_t a0l = Al[ra],     a1l = Al[rb];
            uint32_t a2l = Al[ra + 4], a3l = Al[rb + 4];
            #pragma unroll
            for (int nt = 0; nt < 4; nt++) {
                const int nb = wn * 32 + nt * 8 + gp;
                const int i1 = (k8 + tg) * BPITCH + nb;
                const int i2 = (k8 + tg + 4) * BPITCH + nb;
                uint32_t bh0 = Bh[i1], bh1 = Bh[i2];
                uint32_t bl0 = Bl[i1], bl1 = Bl[i2];
                mma_tf32(acc[nt], a0h, a1h, a2h, a3h, bh0, bh1);
                mma_tf32(acc[nt], a0l, a1l, a2l, a3l, bh0, bh1);
                mma_tf32(acc[nt], a0h, a1h, a2h, a3h, bl0, bl1);
            }
        }
    }

    // epilogue
    const int r0 = m0 + wm * 16 + gp;
    const int r1 = r0 + 8;
    #pragma unroll
    for (int nt = 0; nt < 4; nt++) {
        const int col = n0 + wn * 32 + nt * 8 + 2 * tg;
        const float* bp; int bb;
        if (col < e0)      { bp = b0; bb = 0; }
        else if (col < e1) { bp = b1; bb = e0; }
        else if (col < e2) { bp = b2; bb = e1; }
        else               { bp = b3; bb = e2; }
        float2 bv = *(const float2*)&bp[col - bb];
        float2 o0, o1;
        o0.x = acc[nt][0] + bv.x; o0.y = acc[nt][1] + bv.y;
        o1.x = acc[nt][2] + bv.x; o1.y = acc[nt][3] + bv.y;
        *(float2*)&out[(size_t)r0 * ldo + col] = o0;
        *(float2*)&out[(size_t)r1 * ldo + col] = o1;
    }
}

// ---------------- prep ----------------
__global__ __launch_bounds__(384) void prep_kernel(
    const float* __restrict__ rot, const float* __restrict__ trans,
    const float* __restrict__ head_w)
{
    __shared__ float s_qp3[144];
    __shared__ float s_kp3[144];

    const int n = blockIdx.x;
    const int t = threadIdx.x;
    const float* pr = &g_proj[(size_t)n * PROJ_N];

    if (t < 192) {
        int h = t >> 4, c = t & 15;
        g_kb[((size_t)h * NN + n) * 32 + c] = pr[192 + h * 32 + c];
        g_v[n * 192 + t] = pr[192 + h * 32 + 16 + c];
    }
    float r[9], tr[3];
    #pragma unroll
    for (int e = 0; e < 9; e++) r[e] = rot[n * 9 + e];
    tr[0] = trans[n * 3 + 0]; tr[1] = trans[n * 3 + 1]; tr[2] = trans[n * 3 + 2];

    if (t < 48) {
        float p0 = pr[576 + 0 * 48 + t];
        float p1 = pr[576 + 1 * 48 + t];
        float p2 = pr[576 + 2 * 48 + t];
        #pragma unroll
        for (int ii = 0; ii < 3; ii++)
            s_qp3[t * 3 + ii] = r[ii * 3 + 0] * p0 + r[ii * 3 + 1] * p1 + r[ii * 3 + 2] * p2 + tr[ii];
    }
    if (t >= 64 && t < 208) {
        int u = t - 64;
        float p0 = pr[720 + 0 * 144 + u];
        float p1 = pr[720 + 1 * 144 + u];
        float p2 = pr[720 + 2 * 144 + u];
        int h = u / 12, p = u % 12;
        #pragma unroll
        for (int ii = 0; ii < 3; ii++) {
            float o = r[ii * 3 + 0] * p0 + r[ii * 3 + 1] * p1 + r[ii * 3 + 2] * p2 + tr[ii];
            if (p < 4) s_kp3[(h * 4 + p) * 3 + ii] = o;
            else       g_vpts[n * 288 + (h * 8 + (p - 4)) * 3 + ii] = o;
        }
    }
    __syncthreads();

    {
        int h = t >> 5, e = t & 31;
        float x = head_w[h];
        float hw = ((x > 20.f) ? x : log1pf(__expf(x))) * HWF;

        float qv;
        if (e < 16)       qv = pr[h * 16 + e] * S1;
        else if (e < 28)  qv = s_qp3[h * 12 + (e - 16)] * hw;
        else if (e == 28) qv = -0.5f * hw;
        else if (e == 29) {
            float nq = 0.f;
            #pragma unroll
            for (int d = 0; d < 12; d++) { float v = s_qp3[h * 12 + d]; nq += v * v; }
            qv = -0.5f * hw * nq;
        } else qv = 0.f;
        g_qb[((size_t)h * NN + n) * 32 + e] = qv;

        if (e >= 16) {
            float kv2;
            if (e < 28)       kv2 = s_kp3[h * 12 + (e - 16)];
            else if (e == 28) {
                float nk = 0.f;
                #pragma unroll
                for (int d = 0; d < 12; d++) { float v = s_kp3[h * 12 + d]; nk += v * v; }
                kv2 = nk;
            }
            else if (e == 29) kv2 = 1.f;
            else              kv2 = 0.f;
            g_kb[((size_t)h * NN + n) * 32 + e] = kv2;
        }
    }
}

// ---------------- qkpts ----------------
__global__ __launch_bounds__(256) void qkpts_kernel(const float* __restrict__ mask)
{
    __shared__ float As[32][68];
    __shared__ float Bs[32][68];
    __shared__ float s_mi[64], s_mj[64];

    const int i0 = blockIdx.x * 64;
    const int j0 = blockIdx.y * 64;
    const int h  = blockIdx.z;
    const int t = threadIdx.x;

    #pragma unroll
    for (int r2 = 0; r2 < 2; r2++) {
        int li = t + r2 * 256;
        int row = li >> 3, c4 = (li & 7) * 4;
        float4 a = *(const float4*)&g_qb[((size_t)h * NN + i0 + row) * 32 + c4];
        As[c4 + 0][row] = a.x; As[c4 + 1][row] = a.y;
        As[c4 + 2][row] = a.z; As[c4 + 3][row] = a.w;
        float4 b = *(const float4*)&g_kb[((size_t)h * NN + j0 + row) * 32 + c4];
        Bs[c4 + 0][row] = b.x; Bs[c4 + 1][row] = b.y;
        Bs[c4 + 2][row] = b.z; Bs[c4 + 3][row] = b.w;
    }
    if (t < 64)              s_mi[t] = mask[i0 + t];
    else if (t < 128)        s_mj[t - 64] = mask[j0 + t - 64];
    __syncthreads();

    const int ty = t >> 4, tx = t & 15;
    float acc[4][4] = {};
    #pragma unroll
    for (int k = 0; k < 32; k++) {
        float4 a4 = *(const float4*)&As[k][ty * 4];
        float4 b4 = *(const float4*)&Bs[k][tx * 4];
        acc[0][0] += a4.x * b4.x; acc[0][1] += a4.x * b4.y; acc[0][2] += a4.x * b4.z; acc[0][3] += a4.x * b4.w;
        acc[1][0] += a4.y * b4.x; acc[1][1] += a4.y * b4.y; acc[1][2] += a4.y * b4.z; acc[1][3] += a4.y * b4.w;
        acc[2][0] += a4.z * b4.x; acc[2][1] += a4.z * b4.y; acc[2][2] += a4.z * b4.z; acc[2][3] += a4.z * b4.w;
        acc[3][0] += a4.w * b4.x; acc[3][1] += a4.w * b4.y; acc[3][2] += a4.w * b4.z; acc[3][3] += a4.w * b4.w;
    }
    #pragma unroll
    for (int rr = 0; rr < 4; rr++) {
        float mi = s_mi[ty * 4 + rr];
        float4 o;
        o.x = acc[rr][0] + 100000.f * (mi * s_mj[tx * 4 + 0] - 1.f);
        o.y = acc[rr][1] + 100000.f * (mi * s_mj[tx * 4 + 1] - 1.f);
        o.z = acc[rr][2] + 100000.f * (mi * s_mj[tx * 4 + 2] - 1.f);
        o.w = acc[rr][3] + 100000.f * (mi * s_mj[tx * 4 + 3] - 1.f);
        *(float4*)&g_qkp[(size_t)(i0 + ty * 4 + rr) * 9216 + h * 768 + j0 + tx * 4] = o;
    }
}

// ---------------- bias v2: smem-staged tf32 MMA GEMM [589824 x 128] @ [128 x 12] ----------------
#define BT_TILES (NN * NN / 128)          // 4608
#define BS_SMEM_BYTES (128 * 132 * 4)     // 67584
__global__ __launch_bounds__(256, 2) void bias_kernel(
    const float* __restrict__ z, const float* __restrict__ w_b,
    const float* __restrict__ b_b)
{
    extern __shared__ uint32_t s_z[];     // [128][132] tf32 bits

    const int t = threadIdx.x;
    const int w = t >> 5;
    const int lane = t & 31;
    const int tg = lane & 3;
    const int gp = lane >> 2;

    uint32_t B0[16][2], B1[16][2];
    #pragma unroll
    for (int kk = 0; kk < 16; kk++) {
        int k0 = kk * 8 + tg, k1 = k0 + 4;
        B0[kk][0] = to_tf32(w_b[k0 * 12 + gp]);
        B0[kk][1] = to_tf32(w_b[k1 * 12 + gp]);
        float w10 = (gp < 4) ? w_b[k0 * 12 + 8 + gp] : 0.f;
        float w11 = (gp < 4) ? w_b[k1 * 12 + 8 + gp] : 0.f;
        B1[kk][0] = to_tf32(w10);
        B1[kk][1] = to_tf32(w11);
    }
    const int cb = 2 * tg;
    const float bb0 = b_b[cb], bb1 = b_b[cb + 1];
    const float bb8 = (cb < 4) ? b_b[8 + cb] : 0.f;
    const float bb9 = (cb < 4) ? b_b[9 + cb] : 0.f;

    const int col4 = lane * 4;
    const int rowg = w;

    for (int tile = blockIdx.x; tile < BT_TILES; tile += gridDim.x) {
        const float* zt = z + (size_t)tile * 128 * 128;
        __syncthreads();
        #pragma unroll
        for (int k = 0; k < 16; k++) {
            int row = rowg + k * 8;
            float4 v = __ldg((const float4*)(zt + row * 128 + col4));
            uint4 u;
            u.x = to_tf32(v.x); u.y = to_tf32(v.y);
            u.z = to_tf32(v.z); u.w = to_tf32(v.w);
            *(uint4*)&s_z[row * 132 + col4] = u;
        }
        __syncthreads();

        const uint32_t* sw = s_z + (w * 16) * 132;
        float c0[4] = {0.f, 0.f, 0.f, 0.f};
        float c1[4] = {0.f, 0.f, 0.f, 0.f};
        #pragma unroll
        for (int kk = 0; kk < 16; kk++) {
            int co = kk * 8 + tg;
            uint32_t a0 = sw[gp * 132 + co];
            uint32_t a1 = sw[(gp + 8) * 132 + co];
            uint32_t a2 = sw[gp * 132 + co + 4];
            uint32_t a3 = sw[(gp + 8) * 132 + co + 4];
            mma_tf32(c0, a0, a1, a2, a3, B0[kk][0], B0[kk][1]);
            mma_tf32(c1, a0, a1, a2, a3, B1[kk][0], B1[kk][1]);
        }

        float* outr = g_bias + ((size_t)tile * 128 + w * 16) * 12;
        {
            float2 o;
            o.x = SQ13 * (c0[0] + bb0); o.y = SQ13 * (c0[1] + bb1);
            *(float2*)&outr[gp * 12 + cb] = o;
            o.x = SQ13 * (c0[2] + bb0); o.y = SQ13 * (c0[3] + bb1);
            *(float2*)&outr[(gp + 8) * 12 + cb] = o;
        }
        if (cb < 4) {
            float2 o;
            o.x = SQ13 * (c1[0] + bb8); o.y = SQ13 * (c1[1] + bb9);
            *(float2*)&outr[gp * 12 + 8 + cb] = o;
            o.x = SQ13 * (c1[2] + bb8); o.y = SQ13 * (c1[3] + bb9);
            *(float2*)&outr[(gp + 8) * 12 + 8 + cb] = o;
        }
    }
}

// ---------------- softmax: logits = qkp + bias; softmax per head; write a / aT ----------------
#define LP 772
__global__ __launch_bounds__(256) void softmax_kernel(const float* __restrict__ ss)
{
    __shared__ float s_l[12 * LP];
    __shared__ float s_w[768];

    const int i = blockIdx.x;
    const int t = threadIdx.x;

    for (int idx = t; idx < 9216; idx += 256) {
        int j = idx / 12, h = idx - j * 12;
        s_l[h * LP + j] = g_bias[(size_t)i * 9216 + idx];
    }
    for (int idx = t; idx < 768; idx += 256)
        s_w[idx] = __expf(ss[(size_t)i * 768 + idx]) - 0.99f;
    __syncthreads();
    for (int idx = t; idx < 9216; idx += 256) {
        int h = idx / 768, j = idx - h * 768;
        s_l[h * LP + j] += g_qkp[(size_t)i * 9216 + idx];
    }
    __syncthreads();

    const int wrp = t >> 5, lane = t & 31;
    for (int h = wrp; h < 12; h += 8) {
        float* lr = &s_l[h * LP];
        float m = -1e30f;
        for (int j = lane; j < 768; j += 32) m = fmaxf(m, lr[j]);
        #pragma unroll
        for (int o = 16; o; o >>= 1) m = fmaxf(m, __shfl_xor_sync(0xffffffffu, m, o));
        float sum = 0.f;
        for (int j = lane; j < 768; j += 32) {
            float p = __expf(lr[j] - m) * s_w[j];
            lr[j] = p;
            sum += p;
        }
        #pragma unroll
        for (int o = 16; o; o >>= 1) sum += __shfl_xor_sync(0xffffffffu, sum, o);
        float inv = 1.f / sum;
        for (int j = lane; j < 768; j += 32) lr[j] *= inv;
    }
    __syncthreads();

    for (int idx = t; idx < 9216; idx += 256) {
        int h = idx / 768, j = idx - h * 768;
        g_a[(size_t)i * 9216 + idx] = s_l[h * LP + j];
    }
    for (int idx = t; idx < 9216; idx += 256) {
        int j = idx / 12, h = idx - j * 12;
        g_aT[(size_t)i * 9216 + idx] = s_l[h * LP + j];
    }
}

// ---------------- opair: o_pair[i][h][c] = sum_j a[i][j][h]*z[i][j][c] ----------------
#define OP_SMEM_FLOATS (8 * 12 * 128)
__global__ __launch_bounds__(256) void opair_kernel(const float* __restrict__ z)
{
    extern __shared__ float s_part[];   // [w][12][128]

    const int i = blockIdx.x;
    const int t = threadIdx.x;
    const int w = t >> 5, lane = t & 31;

    ull acc[6][4];
    #pragma unroll
    for (int q = 0; q < 6; q++)
        #pragma unroll
        for (int c = 0; c < 4; c++) acc[q][c] = 0ull;

    const float* zb = z + (size_t)i * 768 * 128 + lane * 4;
    const float* ab = g_aT + (size_t)i * 9216;

    for (int jb = w * 4; jb < 768; jb += 32) {
        float4 zv[4];
        float4 av[4][3];
        #pragma unroll
        for (int u = 0; u < 4; u++) {
            zv[u] = __ldg((const float4*)(zb + (size_t)(jb + u) * 128));
            av[u][0] = __ldg((const float4*)(ab + (jb + u) * 12));
            av[u][1] = __ldg((const float4*)(ab + (jb + u) * 12 + 4));
            av[u][2] = __ldg((const float4*)(ab + (jb + u) * 12 + 8));
        }
        #pragma unroll
        for (int u = 0; u < 4; u++) {
            ull ap[6];
            ap[0] = pack2(av[u][0].x, av[u][0].y);
            ap[1] = pack2(av[u][0].z, av[u][0].w);
            ap[2] = pack2(av[u][1].x, av[u][1].y);
            ap[3] = pack2(av[u][1].z, av[u][1].w);
            ap[4] = pack2(av[u][2].x, av[u][2].y);
            ap[5] = pack2(av[u][2].z, av[u][2].w);
            float zc[4] = {zv[u].x, zv[u].y, zv[u].z, zv[u].w};
            #pragma unroll
            for (int c = 0; c < 4; c++) {
                ull zz = pack2(zc[c], zc[c]);
                #pragma unroll
                for (int q = 0; q < 6; q++)
                    ffma2(acc[q][c], ap[q], zz);
            }
        }
    }

    #pragma unroll
    for (int q = 0; q < 6; q++) {
        #pragma unroll
        for (int c = 0; c < 4; c++) {
            float2 u = unpack2(acc[q][c]);
            s_part[(w * 12 + 2 * q + 0) * 128 + lane * 4 + c] = u.x;
            s_part[(w * 12 + 2 * q + 1) * 128 + lane * 4 + c] = u.y;
        }
    }
    __syncthreads();

    for (int idx = t; idx < 1536; idx += 256) {
        int h = idx >> 7, c = idx & 127;
        float s = 0.f;
        #pragma unroll
        for (int ww = 0; ww < 8; ww++)
            s += s_part[(ww * 12 + h) * 128 + c];
        g_feats[(size_t)i * FEAT_N + 576 + h * 128 + c] = s;
    }
}

// ---------------- ov: 32-row tiles, 128 threads, grid (24,12); s_a pitch 68 ----------------
__global__ __launch_bounds__(128) void ov_kernel()
{
    __shared__ float s_a[32 * 68];
    __shared__ float s_v[64 * 40];

    const int i0 = blockIdx.x * 32;
    const int h  = blockIdx.y;
    const int t = threadIdx.x;
    const int ig = t >> 3;
    const int og = t & 7;

    float acc[2][5] = {};

    for (int j0 = 0; j0 < 768; j0 += 64) {
        #pragma unroll
        for (int it = 0; it < 4; it++) {
            int idx = t + it * 128;
            int row = idx >> 4, q = idx & 15;
            float4 av = *(const float4*)&g_a[((size_t)(i0 + row) * 12 + h) * 768 + j0 + q * 4];
            *(float4*)&s_a[row * 68 + q * 4] = av;
        }
        #pragma unroll
        for (int it = 0; it < 5; it++) {
            int idx = t + it * 128;
            int jj = idx / 10, q = idx - jj * 10;
            float4 vv = (q < 4)
                ? *(const float4*)&g_v[(j0 + jj) * 192 + h * 16 + q * 4]
                : *(const float4*)&g_vpts[(j0 + jj) * 288 + h * 24 + (q - 4) * 4];
            *(float4*)&s_v[jj * 40 + q * 4] = vv;
        }
        __syncthreads();
        #pragma unroll 8
        for (int jj = 0; jj < 64; jj++) {
            float a0 = s_a[(ig * 2 + 0) * 68 + jj];
            float a1 = s_a[(ig * 2 + 1) * 68 + jj];
            const float* vp = &s_v[jj * 40 + og * 5];
            #pragma unroll
            for (int u = 0; u < 5; u++) {
                float vv = vp[u];
                acc[0][u] += a0 * vv;
                acc[1][u] += a1 * vv;
            }
        }
        __syncthreads();
    }
    #pragma unroll
    for (int r = 0; r < 2; r++) {
        int n = i0 + ig * 2 + r;
        #pragma unroll
        for (int u = 0; u < 5; u++) {
            int e = og * 5 + u;
            if (e < 16) g_feats[(size_t)n * FEAT_N + h * 16 + e] = acc[r][u];
            else        g_optg[n * 288 + h * 24 + (e - 16)] = acc[r][u];
        }
    }
}

// ---------------- optfinal ----------------
__global__ __launch_bounds__(96) void optfinal_kernel(
    const float* __restrict__ rot, const float* __restrict__ trans)
{
    const int n = blockIdx.x;
    const int hp = threadIdx.x;
    float r[9], tr[3];
    #pragma unroll
    for (int e = 0; e < 9; e++) r[e] = rot[n * 9 + e];
    tr[0] = trans[n * 3 + 0]; tr[1] = trans[n * 3 + 1]; tr[2] = trans[n * 3 + 2];

    float gx = g_optg[n * 288 + hp * 3 + 0] - tr[0];
    float gy = g_optg[n * 288 + hp * 3 + 1] - tr[1];
    float gz = g_optg[n * 288 + hp * 3 + 2] - tr[2];
    float l0 = r[0] * gx + r[3] * gy + r[6] * gz;
    float l1 = r[1] * gx + r[4] * gy + r[7] * gz;
    float l2 = r[2] * gx + r[5] * gy + r[8] * gz;

    float* f = &g_feats[(size_t)n * FEAT_N];
    f[192 + hp] = l0;
    f[288 + hp] = l1;
    f[384 + hp] = l2;
    f[480 + hp] = sqrtf(l0 * l0 + l1 * l1 + l2 * l2 + 1e-8f);
}

// ---------------- launch ----------------
extern "C" void kernel_launch(void* const* d_in, const int* in_sizes, int n_in,
                              void* d_out, int out_size)
{
    const float* s       = (const float*)d_in[0];
    const float* z       = (const float*)d_in[1];
    const float* rot     = (const float*)d_in[2];
    const float* trans   = (const float*)d_in[3];
    const float* mask    = (const float*)d_in[4];
    const float* ss      = (const float*)d_in[5];
    const float* w_q     = (const float*)d_in[6];
    const float* b_q     = (const float*)d_in[7];
    const float* w_kv    = (const float*)d_in[8];
    const float* b_kv    = (const float*)d_in[9];
    const float* w_qp    = (const float*)d_in[10];
    const float* b_qp    = (const float*)d_in[11];
    const float* w_kvp   = (const float*)d_in[12];
    const float* b_kvp   = (const float*)d_in[13];
    const float* w_b     = (const float*)d_in[14];
    const float* b_b     = (const float*)d_in[15];
    const float* head_w  = (const float*)d_in[16];
    const float* w_out   = (const float*)d_in[17];
    const float* b_out   = (const float*)d_in[18];
    float* out = (float*)d_out;

    float* proj;  cudaGetSymbolAddress((void**)&proj, g_proj);
    float* feats; cudaGetSymbolAddress((void**)&feats, g_feats);

    static bool attr_done = false;
    if (!attr_done) {
        cudaFuncSetAttribute(opair_kernel,
                             cudaFuncAttributeMaxDynamicSharedMemorySize,
                             OP_SMEM_FLOATS * 4);
        cudaFuncSetAttribute(bias_kernel,
                             cudaFuncAttributeMaxDynamicSharedMemorySize,
                             BS_SMEM_BYTES);
        attr_done = true;
    }

    // K1: projections (768 x 1152) via 3xTF32 MMA
    gemm_mma_kernel<<<dim3(18, 12), 256>>>(
        s, CS, w_q, w_kv, w_qp, w_kvp, b_q, b_kv, b_qp, b_kvp,
        192, 576, 720, 1152, proj, PROJ_N);

    // K2: split k/v, rotate points, build logit-GEMM rows
    prep_kernel<<<NN, 384>>>(rot, trans, head_w);

    // K2b: qk+pts+mask logits as 30-dim GEMM
    qkpts_kernel<<<dim3(12, 12, 12), 256>>>(mask);

    // K3a: z-bias via smem-staged tf32 MMA (z pass 1)
    bias_kernel<<<296, 256, BS_SMEM_BYTES>>>(z, w_b, b_b);

    // K3b: softmax
    softmax_kernel<<<NN, 256>>>(ss);

    // K3c: o_pair (z pass 2)
    opair_kernel<<<NN, 256, OP_SMEM_FLOATS * 4>>>(z);

    // K4: o and o_pt accumulation
    ov_kernel<<<dim3(24, 12), 128>>>();

    // K5: finalize o_pt + norms
    optfinal_kernel<<<NN, 96>>>(rot, trans);

    // K6: output GEMM (768 x 384, K=2112) via 3xTF32 MMA
    gemm_mma_kernel<<<dim3(6, 12), 256>>>(
        feats, FEAT_N, w_out, w_out, w_out, w_out, b_out, b_out, b_out, b_out,
        384, 384, 384, 384, out, CS);
}

// round 15
// speedup vs baseline: 1.1113x; 1.0971x over previous
#include <cuda_runtime.h>
#include <math.h>
#include <stdint.h>

#define NN 768
#define HH 12
#define CS 384
#define PROJ_N 1152
#define FEAT_N 2112   // [o 192 | ptx 96 | pty 96 | ptz 96 | ptnorm 96 | opair 1536]

typedef unsigned long long ull;

#define S1 0.14433756729740643f      // sqrt(1/48)
#define SQ13 0.5773502691896258f     // sqrt(1/3)
#define HWF 0.13608276348795434f     // sqrt(1/54)

__device__ __forceinline__ void ffma2(ull& d, ull a, ull b) {
    asm("fma.rn.f32x2 %0, %1, %2, %0;" : "+l"(d) : "l"(a), "l"(b));
}
__device__ __forceinline__ ull pack2(float x, float y) {
    ull r; asm("mov.b64 %0, {%1, %2};" : "=l"(r) : "f"(x), "f"(y)); return r;
}
__device__ __forceinline__ float2 unpack2(ull v) {
    float2 r; asm("mov.b64 {%0, %1}, %2;" : "=f"(r.x), "=f"(r.y) : "l"(v)); return r;
}
__device__ __forceinline__ uint32_t to_tf32(float f) {
    uint32_t r; asm("cvt.rna.tf32.f32 %0, %1;" : "=r"(r) : "f"(f)); return r;
}
__device__ __forceinline__ void mma_tf32(float c[4],
    uint32_t a0, uint32_t a1, uint32_t a2, uint32_t a3,
    uint32_t b0, uint32_t b1)
{
    asm("mma.sync.aligned.m16n8k8.row.col.f32.tf32.tf32.f32 "
        "{%0,%1,%2,%3}, {%4,%5,%6,%7}, {%8,%9}, {%0,%1,%2,%3};"
        : "+f"(c[0]), "+f"(c[1]), "+f"(c[2]), "+f"(c[3])
        : "r"(a0), "r"(a1), "r"(a2), "r"(a3), "r"(b0), "r"(b1));
}

// ---------------- scratch ----------------
__device__ float g_proj[NN * PROJ_N];
__device__ float g_v[NN * 192];
__device__ float g_vpts[NN * 288];
__device__ float g_qb[HH * NN * 32];
__device__ float g_kb[HH * NN * 32];
__device__ float g_qkp[(size_t)NN * HH * NN]; // [i][h][j]
__device__ float g_bias[(size_t)NN * NN * HH];// [i][j][h]
__device__ float g_a[(size_t)NN * HH * NN];   // [i][h][j]
__device__ float g_optg[NN * 288];
__device__ float g_feats[NN * FEAT_N];

// ---------------- GEMM via 3xTF32 MMA: out = A @ W + bias, segmented over N ----------------
#define APITCH 20
#define BPITCH 72
__global__ __launch_bounds__(256) void gemm_mma_kernel(
    const float* __restrict__ A, int K,
    const float* __restrict__ w0, const float* __restrict__ w1,
    const float* __restrict__ w2, const float* __restrict__ w3,
    const float* __restrict__ b0, const float* __restrict__ b1,
    const float* __restrict__ b2, const float* __restrict__ b3,
    int e0, int e1, int e2, int e3,
    float* __restrict__ out, int ldo)
{
    __shared__ uint32_t Ah[64 * APITCH], Al[64 * APITCH];
    __shared__ uint32_t Bh[16 * BPITCH], Bl[16 * BPITCH];

    const int m0 = blockIdx.y * 64;
    const int n0 = blockIdx.x * 64;
    const int t = threadIdx.x;
    const int warp = t >> 5, lane = t & 31;
    const int wm = warp & 3, wn = warp >> 2;
    const int tg = lane & 3, gp = lane >> 2;

    const int brow = t >> 4;
    const int bn = (t & 15) * 4;
    const int ncol = n0 + bn;
    const float* W; int base, segN;
    if (ncol < e0)      { W = w0; base = 0;  segN = e0; }
    else if (ncol < e1) { W = w1; base = e0; segN = e1 - e0; }
    else if (ncol < e2) { W = w2; base = e1; segN = e2 - e1; }
    else                { W = w3; base = e2; segN = e3 - e2; }

    const int ar = t >> 2, ak = (t & 3) * 4;

    float acc[4][4] = {};

    for (int k0 = 0; k0 < K; k0 += 16) {
        __syncthreads();
        {
            float4 v = *(const float4*)&A[(size_t)(m0 + ar) * K + k0 + ak];
            uint4 hi, lo;
            hi.x = to_tf32(v.x); lo.x = to_tf32(v.x - __uint_as_float(hi.x));
            hi.y = to_tf32(v.y); lo.y = to_tf32(v.y - __uint_as_float(hi.y));
            hi.z = to_tf32(v.z); lo.z = to_tf32(v.z - __uint_as_float(hi.z));
            hi.w = to_tf32(v.w); lo.w = to_tf32(v.w - __uint_as_float(hi.w));
            *(uint4*)&Ah[ar * APITCH + ak] = hi;
            *(uint4*)&Al[ar * APITCH + ak] = lo;
        }
        {
            float4 v = *(const float4*)&W[(size_t)(k0 + brow) * segN + (ncol - base)];
            uint4 hi, lo;
            hi.x = to_tf32(v.x); lo.x = to_tf32(v.x - __uint_as_float(hi.x));
            hi.y = to_tf32(v.y); lo.y = to_tf32(v.y - __uint_as_float(hi.y));
            hi.z = to_tf32(v.z); lo.z = to_tf32(v.z - __uint_as_float(hi.z));
            hi.w = to_tf32(v.w); lo.w = to_tf32(v.w - __uint_as_float(hi.w));
            *(uint4*)&Bh[brow * BPITCH + bn] = hi;
            *(uint4*)&Bl[brow * BPITCH + bn] = lo;
        }
        __syncthreads();

        #pragma unroll
        for (int kk = 0; kk < 2; kk++) {
            const int k8 = kk * 8;
            const int ra = (wm * 16 + gp) * APITCH + k8 + tg;
            const int rb = (wm * 16 + gp + 8) * APITCH + k8 + tg;
            uint32_t a0h = Ah[ra],     a1h = Ah[rb];
            uint32_t a2h = Ah[ra + 4], a3h = Ah[rb + 4];
            uint32_t a0l = Al[ra],     a1l = Al[rb];
            uint32_t a2l = Al[ra + 4], a3l = Al[rb + 4];
            #pragma unroll
            for (int nt = 0; nt < 4; nt++) {
                const int nb = wn * 32 + nt * 8 + gp;
                const int i1 = (k8 + tg) * BPITCH + nb;
                const int i2 = (k8 + tg + 4) * BPITCH + nb;
                uint32_t bh0 = Bh[i1], bh1 = Bh[i2];
                uint32_t bl0 = Bl[i1], bl1 = Bl[i2];
                mma_tf32(acc[nt], a0h, a1h, a2h, a3h, bh0, bh1);
                mma_tf32(acc[nt], a0l, a1l, a2l, a3l, bh0, bh1);
                mma_tf32(acc[nt], a0h, a1h, a2h, a3h, bl0, bl1);
            }
        }
    }

    const int r0 = m0 + wm * 16 + gp;
    const int r1 = r0 + 8;
    #pragma unroll
    for (int nt = 0; nt < 4; nt++) {
        const int col = n0 + wn * 32 + nt * 8 + 2 * tg;
        const float* bp; int bb;
        if (col < e0)      { bp = b0; bb = 0; }
        else if (col < e1) { bp = b1; bb = e0; }
        else if (col < e2) { bp = b2; bb = e1; }
        else               { bp = b3; bb = e2; }
        float2 bv = *(const float2*)&bp[col - bb];
        float2 o0, o1;
        o0.x = acc[nt][0] + bv.x; o0.y = acc[nt][1] + bv.y;
        o1.x = acc[nt][2] + bv.x; o1.y = acc[nt][3] + bv.y;
        *(float2*)&out[(size_t)r0 * ldo + col] = o0;
        *(float2*)&out[(size_t)r1 * ldo + col] = o1;
    }
}

// ---------------- prep ----------------
__global__ __launch_bounds__(384) void prep_kernel(
    const float* __restrict__ rot, const float* __restrict__ trans,
    const float* __restrict__ head_w)
{
    __shared__ float s_qp3[144];
    __shared__ float s_kp3[144];

    const int n = blockIdx.x;
    const int t = threadIdx.x;
    const float* pr = &g_proj[(size_t)n * PROJ_N];

    if (t < 192) {
        int h = t >> 4, c = t & 15;
        g_kb[((size_t)h * NN + n) * 32 + c] = pr[192 + h * 32 + c];
        g_v[n * 192 + t] = pr[192 + h * 32 + 16 + c];
    }
    float r[9], tr[3];
    #pragma unroll
    for (int e = 0; e < 9; e++) r[e] = rot[n * 9 + e];
    tr[0] = trans[n * 3 + 0]; tr[1] = trans[n * 3 + 1]; tr[2] = trans[n * 3 + 2];

    if (t < 48) {
        float p0 = pr[576 + 0 * 48 + t];
        float p1 = pr[576 + 1 * 48 + t];
        float p2 = pr[576 + 2 * 48 + t];
        #pragma unroll
        for (int ii = 0; ii < 3; ii++)
            s_qp3[t * 3 + ii] = r[ii * 3 + 0] * p0 + r[ii * 3 + 1] * p1 + r[ii * 3 + 2] * p2 + tr[ii];
    }
    if (t >= 64 && t < 208) {
        int u = t - 64;
        float p0 = pr[720 + 0 * 144 + u];
        float p1 = pr[720 + 1 * 144 + u];
        float p2 = pr[720 + 2 * 144 + u];
        int h = u / 12, p = u % 12;
        #pragma unroll
        for (int ii = 0; ii < 3; ii++) {
            float o = r[ii * 3 + 0] * p0 + r[ii * 3 + 1] * p1 + r[ii * 3 + 2] * p2 + tr[ii];
            if (p < 4) s_kp3[(h * 4 + p) * 3 + ii] = o;
            else       g_vpts[n * 288 + (h * 8 + (p - 4)) * 3 + ii] = o;
        }
    }
    __syncthreads();

    {
        int h = t >> 5, e = t & 31;
        float x = head_w[h];
        float hw = ((x > 20.f) ? x : log1pf(__expf(x))) * HWF;

        float qv;
        if (e < 16)       qv = pr[h * 16 + e] * S1;
        else if (e < 28)  qv = s_qp3[h * 12 + (e - 16)] * hw;
        else if (e == 28) qv = -0.5f * hw;
        else if (e == 29) {
            float nq = 0.f;
            #pragma unroll
            for (int d = 0; d < 12; d++) { float v = s_qp3[h * 12 + d]; nq += v * v; }
            qv = -0.5f * hw * nq;
        } else qv = 0.f;
        g_qb[((size_t)h * NN + n) * 32 + e] = qv;

        if (e >= 16) {
            float kv2;
            if (e < 28)       kv2 = s_kp3[h * 12 + (e - 16)];
            else if (e == 28) {
                float nk = 0.f;
                #pragma unroll
                for (int d = 0; d < 12; d++) { float v = s_kp3[h * 12 + d]; nk += v * v; }
                kv2 = nk;
            }
            else if (e == 29) kv2 = 1.f;
            else              kv2 = 0.f;
            g_kb[((size_t)h * NN + n) * 32 + e] = kv2;
        }
    }
}

// ---------------- qkpts ----------------
__global__ __launch_bounds__(256) void qkpts_kernel(const float* __restrict__ mask)
{
    __shared__ float As[32][68];
    __shared__ float Bs[32][68];
    __shared__ float s_mi[64], s_mj[64];

    const int i0 = blockIdx.x * 64;
    const int j0 = blockIdx.y * 64;
    const int h  = blockIdx.z;
    const int t = threadIdx.x;

    #pragma unroll
    for (int r2 = 0; r2 < 2; r2++) {
        int li = t + r2 * 256;
        int row = li >> 3, c4 = (li & 7) * 4;
        float4 a = *(const float4*)&g_qb[((size_t)h * NN + i0 + row) * 32 + c4];
        As[c4 + 0][row] = a.x; As[c4 + 1][row] = a.y;
        As[c4 + 2][row] = a.z; As[c4 + 3][row] = a.w;
        float4 b = *(const float4*)&g_kb[((size_t)h * NN + j0 + row) * 32 + c4];
        Bs[c4 + 0][row] = b.x; Bs[c4 + 1][row] = b.y;
        Bs[c4 + 2][row] = b.z; Bs[c4 + 3][row] = b.w;
    }
    if (t < 64)              s_mi[t] = mask[i0 + t];
    else if (t < 128)        s_mj[t - 64] = mask[j0 + t - 64];
    __syncthreads();

    const int ty = t >> 4, tx = t & 15;
    float acc[4][4] = {};
    #pragma unroll
    for (int k = 0; k < 32; k++) {
        float4 a4 = *(const float4*)&As[k][ty * 4];
        float4 b4 = *(const float4*)&Bs[k][tx * 4];
        acc[0][0] += a4.x * b4.x; acc[0][1] += a4.x * b4.y; acc[0][2] += a4.x * b4.z; acc[0][3] += a4.x * b4.w;
        acc[1][0] += a4.y * b4.x; acc[1][1] += a4.y * b4.y; acc[1][2] += a4.y * b4.z; acc[1][3] += a4.y * b4.w;
        acc[2][0] += a4.z * b4.x; acc[2][1] += a4.z * b4.y; acc[2][2] += a4.z * b4.z; acc[2][3] += a4.z * b4.w;
        acc[3][0] += a4.w * b4.x; acc[3][1] += a4.w * b4.y; acc[3][2] += a4.w * b4.z; acc[3][3] += a4.w * b4.w;
    }
    #pragma unroll
    for (int rr = 0; rr < 4; rr++) {
        float mi = s_mi[ty * 4 + rr];
        float4 o;
        o.x = acc[rr][0] + 100000.f * (mi * s_mj[tx * 4 + 0] - 1.f);
        o.y = acc[rr][1] + 100000.f * (mi * s_mj[tx * 4 + 1] - 1.f);
        o.z = acc[rr][2] + 100000.f * (mi * s_mj[tx * 4 + 2] - 1.f);
        o.w = acc[rr][3] + 100000.f * (mi * s_mj[tx * 4 + 3] - 1.f);
        *(float4*)&g_qkp[(size_t)(i0 + ty * 4 + rr) * 9216 + h * 768 + j0 + tx * 4] = o;
    }
}

// ---------------- bias v2: smem-staged tf32 MMA GEMM ----------------
#define BT_TILES (NN * NN / 128)          // 4608
#define BS_SMEM_BYTES (128 * 132 * 4)     // 67584
__global__ __launch_bounds__(256, 2) void bias_kernel(
    const float* __restrict__ z, const float* __restrict__ w_b,
    const float* __restrict__ b_b)
{
    extern __shared__ uint32_t s_z[];     // [128][132] tf32 bits

    const int t = threadIdx.x;
    const int w = t >> 5;
    const int lane = t & 31;
    const int tg = lane & 3;
    const int gp = lane >> 2;

    uint32_t B0[16][2], B1[16][2];
    #pragma unroll
    for (int kk = 0; kk < 16; kk++) {
        int k0 = kk * 8 + tg, k1 = k0 + 4;
        B0[kk][0] = to_tf32(w_b[k0 * 12 + gp]);
        B0[kk][1] = to_tf32(w_b[k1 * 12 + gp]);
        float w10 = (gp < 4) ? w_b[k0 * 12 + 8 + gp] : 0.f;
        float w11 = (gp < 4) ? w_b[k1 * 12 + 8 + gp] : 0.f;
        B1[kk][0] = to_tf32(w10);
        B1[kk][1] = to_tf32(w11);
    }
    const int cb = 2 * tg;
    const float bb0 = b_b[cb], bb1 = b_b[cb + 1];
    const float bb8 = (cb < 4) ? b_b[8 + cb] : 0.f;
    const float bb9 = (cb < 4) ? b_b[9 + cb] : 0.f;

    const int col4 = lane * 4;
    const int rowg = w;

    for (int tile = blockIdx.x; tile < BT_TILES; tile += gridDim.x) {
        const float* zt = z + (size_t)tile * 128 * 128;
        __syncthreads();
        #pragma unroll
        for (int k = 0; k < 16; k++) {
            int row = rowg + k * 8;
            float4 v = __ldg((const float4*)(zt + row * 128 + col4));
            uint4 u;
            u.x = to_tf32(v.x); u.y = to_tf32(v.y);
            u.z = to_tf32(v.z); u.w = to_tf32(v.w);
            *(uint4*)&s_z[row * 132 + col4] = u;
        }
        __syncthreads();

        const uint32_t* sw = s_z + (w * 16) * 132;
        float c0[4] = {0.f, 0.f, 0.f, 0.f};
        float c1[4] = {0.f, 0.f, 0.f, 0.f};
        #pragma unroll
        for (int kk = 0; kk < 16; kk++) {
            int co = kk * 8 + tg;
            uint32_t a0 = sw[gp * 132 + co];
            uint32_t a1 = sw[(gp + 8) * 132 + co];
            uint32_t a2 = sw[gp * 132 + co + 4];
            uint32_t a3 = sw[(gp + 8) * 132 + co + 4];
            mma_tf32(c0, a0, a1, a2, a3, B0[kk][0], B0[kk][1]);
            mma_tf32(c1, a0, a1, a2, a3, B1[kk][0], B1[kk][1]);
        }

        float* outr = g_bias + ((size_t)tile * 128 + w * 16) * 12;
        {
            float2 o;
            o.x = SQ13 * (c0[0] + bb0); o.y = SQ13 * (c0[1] + bb1);
            *(float2*)&outr[gp * 12 + cb] = o;
            o.x = SQ13 * (c0[2] + bb0); o.y = SQ13 * (c0[3] + bb1);
            *(float2*)&outr[(gp + 8) * 12 + cb] = o;
        }
        if (cb < 4) {
            float2 o;
            o.x = SQ13 * (c1[0] + bb8); o.y = SQ13 * (c1[1] + bb9);
            *(float2*)&outr[gp * 12 + 8 + cb] = o;
            o.x = SQ13 * (c1[2] + bb8); o.y = SQ13 * (c1[3] + bb9);
            *(float2*)&outr[(gp + 8) * 12 + 8 + cb] = o;
        }
    }
}

// ---------------- smopair: softmax + o_pair fused, block = one i ----------------
// Phase 1: logits = bias + qkp -> softmax -> g_a. Phase 2: o_pair from s_l probs + z stream.
#define LP 772
#define SO_SMEM_FLOATS (12 * LP + 768 + 8 * 12 * 128)
__global__ __launch_bounds__(256) void smopair_kernel(
    const float* __restrict__ z, const float* __restrict__ ss)
{
    extern __shared__ float smf[];
    float* s_l    = smf;                    // [12][LP] logits -> probs
    float* s_w    = smf + 12 * LP;          // [768]
    float* s_part = s_w + 768;              // [8][12][128]

    const int i = blockIdx.x;
    const int t = threadIdx.x;
    const int w = t >> 5, lane = t & 31;

    // ---- phase 1: load bias + qkp, softmax ----
    for (int idx = t; idx < 9216; idx += 256) {
        int j = idx / 12, h = idx - j * 12;
        s_l[h * LP + j] = g_bias[(size_t)i * 9216 + idx];
    }
    for (int idx = t; idx < 768; idx += 256)
        s_w[idx] = __expf(ss[(size_t)i * 768 + idx]) - 0.99f;
    __syncthreads();
    for (int idx = t; idx < 9216; idx += 256) {
        int h = idx / 768, j = idx - h * 768;
        s_l[h * LP + j] += g_qkp[(size_t)i * 9216 + idx];
    }
    __syncthreads();

    for (int h = w; h < 12; h += 8) {
        float* lr = &s_l[h * LP];
        float m = -1e30f;
        for (int j = lane; j < 768; j += 32) m = fmaxf(m, lr[j]);
        #pragma unroll
        for (int o = 16; o; o >>= 1) m = fmaxf(m, __shfl_xor_sync(0xffffffffu, m, o));
        float sum = 0.f;
        for (int j = lane; j < 768; j += 32) {
            float p = __expf(lr[j] - m) * s_w[j];
            lr[j] = p;
            sum += p;
        }
        #pragma unroll
        for (int o = 16; o; o >>= 1) sum += __shfl_xor_sync(0xffffffffu, sum, o);
        float inv = 1.f / sum;
        for (int j = lane; j < 768; j += 32) lr[j] *= inv;
    }
    __syncthreads();

    // ---- phase 2: o_pair accumulate (z stream; a read from s_l via broadcast LDS) ----
    ull acc[6][4];
    #pragma unroll
    for (int q = 0; q < 6; q++)
        #pragma unroll
        for (int c = 0; c < 4; c++) acc[q][c] = 0ull;

    const float* zb = z + (size_t)i * 768 * 128 + lane * 4;

    for (int jb = w * 4; jb < 768; jb += 32) {
        float4 zv[4];
        #pragma unroll
        for (int u = 0; u < 4; u++)
            zv[u] = __ldg((const float4*)(zb + (size_t)(jb + u) * 128));
        #pragma unroll
        for (int u = 0; u < 4; u++) {
            const int j = jb + u;
            ull ap[6];
            #pragma unroll
            for (int q = 0; q < 6; q++)
                ap[q] = pack2(s_l[(2 * q) * LP + j], s_l[(2 * q + 1) * LP + j]);
            float zc[4] = {zv[u].x, zv[u].y, zv[u].z, zv[u].w};
            #pragma unroll
            for (int c = 0; c < 4; c++) {
                ull zz = pack2(zc[c], zc[c]);
                #pragma unroll
                for (int q = 0; q < 6; q++)
                    ffma2(acc[q][c], ap[q], zz);
            }
        }
    }

    // write a for ov kernel ([h][j] layout)
    for (int idx = t; idx < 9216; idx += 256) {
        int h = idx / 768, j = idx - h * 768;
        g_a[(size_t)i * 9216 + idx] = s_l[h * LP + j];
    }

    // partials + cross-warp reduce
    #pragma unroll
    for (int q = 0; q < 6; q++) {
        #pragma unroll
        for (int c = 0; c < 4; c++) {
            float2 u = unpack2(acc[q][c]);
            s_part[(w * 12 + 2 * q + 0) * 128 + lane * 4 + c] = u.x;
            s_part[(w * 12 + 2 * q + 1) * 128 + lane * 4 + c] = u.y;
        }
    }
    __syncthreads();

    for (int idx = t; idx < 1536; idx += 256) {
        int h = idx >> 7, c = idx & 127;
        float s = 0.f;
        #pragma unroll
        for (int ww = 0; ww < 8; ww++)
            s += s_part[(ww * 12 + h) * 128 + c];
        g_feats[(size_t)i * FEAT_N + 576 + h * 128 + c] = s;
    }
}

// ---------------- ov: 32-row tiles, 128 threads, grid (24,12); s_a pitch 68 ----------------
__global__ __launch_bounds__(128) void ov_kernel()
{
    __shared__ float s_a[32 * 68];
    __shared__ float s_v[64 * 40];

    const int i0 = blockIdx.x * 32;
    const int h  = blockIdx.y;
    const int t = threadIdx.x;
    const int ig = t >> 3;
    const int og = t & 7;

    float acc[2][5] = {};

    for (int j0 = 0; j0 < 768; j0 += 64) {
        #pragma unroll
        for (int it = 0; it < 4; it++) {
            int idx = t + it * 128;
            int row = idx >> 4, q = idx & 15;
            float4 av = *(const float4*)&g_a[((size_t)(i0 + row) * 12 + h) * 768 + j0 + q * 4];
            *(float4*)&s_a[row * 68 + q * 4] = av;
        }
        #pragma unroll
        for (int it = 0; it < 5; it++) {
            int idx = t + it * 128;
            int jj = idx / 10, q = idx - jj * 10;
            float4 vv = (q < 4)
                ? *(const float4*)&g_v[(j0 + jj) * 192 + h * 16 + q * 4]
                : *(const float4*)&g_vpts[(j0 + jj) * 288 + h * 24 + (q - 4) * 4];
            *(float4*)&s_v[jj * 40 + q * 4] = vv;
        }
        __syncthreads();
        #pragma unroll 8
        for (int jj = 0; jj < 64; jj++) {
            float a0 = s_a[(ig * 2 + 0) * 68 + jj];
            float a1 = s_a[(ig * 2 + 1) * 68 + jj];
            const float* vp = &s_v[jj * 40 + og * 5];
            #pragma unroll
            for (int u = 0; u < 5; u++) {
                float vv = vp[u];
                acc[0][u] += a0 * vv;
                acc[1][u] += a1 * vv;
            }
        }
        __syncthreads();
    }
    #pragma unroll
    for (int r = 0; r < 2; r++) {
        int n = i0 + ig * 2 + r;
        #pragma unroll
        for (int u = 0; u < 5; u++) {
            int e = og * 5 + u;
            if (e < 16) g_feats[(size_t)n * FEAT_N + h * 16 + e] = acc[r][u];
            else        g_optg[n * 288 + h * 24 + (e - 16)] = acc[r][u];
        }
    }
}

// ---------------- optfinal ----------------
__global__ __launch_bounds__(96) void optfinal_kernel(
    const float* __restrict__ rot, const float* __restrict__ trans)
{
    const int n = blockIdx.x;
    const int hp = threadIdx.x;
    float r[9], tr[3];
    #pragma unroll
    for (int e = 0; e < 9; e++) r[e] = rot[n * 9 + e];
    tr[0] = trans[n * 3 + 0]; tr[1] = trans[n * 3 + 1]; tr[2] = trans[n * 3 + 2];

    float gx = g_optg[n * 288 + hp * 3 + 0] - tr[0];
    float gy = g_optg[n * 288 + hp * 3 + 1] - tr[1];
    float gz = g_optg[n * 288 + hp * 3 + 2] - tr[2];
    float l0 = r[0] * gx + r[3] * gy + r[6] * gz;
    float l1 = r[1] * gx + r[4] * gy + r[7] * gz;
    float l2 = r[2] * gx + r[5] * gy + r[8] * gz;

    float* f = &g_feats[(size_t)n * FEAT_N];
    f[192 + hp] = l0;
    f[288 + hp] = l1;
    f[384 + hp] = l2;
    f[480 + hp] = sqrtf(l0 * l0 + l1 * l1 + l2 * l2 + 1e-8f);
}

// ---------------- launch ----------------
extern "C" void kernel_launch(void* const* d_in, const int* in_sizes, int n_in,
                              void* d_out, int out_size)
{
    const float* s       = (const float*)d_in[0];
    const float* z       = (const float*)d_in[1];
    const float* rot     = (const float*)d_in[2];
    const float* trans   = (const float*)d_in[3];
    const float* mask    = (const float*)d_in[4];
    const float* ss      = (const float*)d_in[5];
    const float* w_q     = (const float*)d_in[6];
    const float* b_q     = (const float*)d_in[7];
    const float* w_kv    = (const float*)d_in[8];
    const float* b_kv    = (const float*)d_in[9];
    const float* w_qp    = (const float*)d_in[10];
    const float* b_qp    = (const float*)d_in[11];
    const float* w_kvp   = (const float*)d_in[12];
    const float* b_kvp   = (const float*)d_in[13];
    const float* w_b     = (const float*)d_in[14];
    const float* b_b     = (const float*)d_in[15];
    const float* head_w  = (const float*)d_in[16];
    const float* w_out   = (const float*)d_in[17];
    const float* b_out   = (const float*)d_in[18];
    float* out = (float*)d_out;

    float* proj;  cudaGetSymbolAddress((void**)&proj, g_proj);
    float* feats; cudaGetSymbolAddress((void**)&feats, g_feats);

    static bool attr_done = false;
    if (!attr_done) {
        cudaFuncSetAttribute(smopair_kernel,
                             cudaFuncAttributeMaxDynamicSharedMemorySize,
                             SO_SMEM_FLOATS * 4);
        cudaFuncSetAttribute(bias_kernel,
                             cudaFuncAttributeMaxDynamicSharedMemorySize,
                             BS_SMEM_BYTES);
        attr_done = true;
    }

    // K1: projections (768 x 1152) via 3xTF32 MMA
    gemm_mma_kernel<<<dim3(18, 12), 256>>>(
        s, CS, w_q, w_kv, w_qp, w_kvp, b_q, b_kv, b_qp, b_kvp,
        192, 576, 720, 1152, proj, PROJ_N);

    // K2: split k/v, rotate points, build logit-GEMM rows
    prep_kernel<<<NN, 384>>>(rot, trans, head_w);

    // K2b: qk+pts+mask logits as 30-dim GEMM
    qkpts_kernel<<<dim3(12, 12, 12), 256>>>(mask);

    // K3a: z-bias via smem-staged tf32 MMA (z pass 1)
    bias_kernel<<<296, 256, BS_SMEM_BYTES>>>(z, w_b, b_b);

    // K3b: fused softmax + o_pair (z pass 2)
    smopair_kernel<<<NN, 256, SO_SMEM_FLOATS * 4>>>(z, ss);

    // K4: o and o_pt accumulation
    ov_kernel<<<dim3(24, 12), 128>>>();

    // K5: finalize o_pt + norms
    optfinal_kernel<<<NN, 96>>>(rot, trans);

    // K6: output GEMM (768 x 384, K=2112) via 3xTF32 MMA
    gemm_mma_kernel<<<dim3(6, 12), 256>>>(
        feats, FEAT_N, w_out, w_out, w_out, w_out, b_out, b_out, b_out, b_out,
        384, 384, 384, 384, out, CS);
}

// round 16
// speedup vs baseline: 1.1385x; 1.0245x over previous
#include <cuda_runtime.h>
#include <math.h>
#include <stdint.h>

#define NN 768
#define HH 12
#define CS 384
#define PROJ_N 1152
#define FEAT_N 2112   // [o 192 | ptx 96 | pty 96 | ptz 96 | ptnorm 96 | opair 1536]

typedef unsigned long long ull;

#define S1 0.14433756729740643f      // sqrt(1/48)
#define SQ13 0.5773502691896258f     // sqrt(1/3)
#define HWF 0.13608276348795434f     // sqrt(1/54)

__device__ __forceinline__ void ffma2(ull& d, ull a, ull b) {
    asm("fma.rn.f32x2 %0, %1, %2, %0;" : "+l"(d) : "l"(a), "l"(b));
}
__device__ __forceinline__ ull pack2(float x, float y) {
    ull r; asm("mov.b64 %0, {%1, %2};" : "=l"(r) : "f"(x), "f"(y)); return r;
}
__device__ __forceinline__ float2 unpack2(ull v) {
    float2 r; asm("mov.b64 {%0, %1}, %2;" : "=f"(r.x), "=f"(r.y) : "l"(v)); return r;
}
__device__ __forceinline__ uint32_t to_tf32(float f) {
    uint32_t r; asm("cvt.rna.tf32.f32 %0, %1;" : "=r"(r) : "f"(f)); return r;
}
__device__ __forceinline__ void mma_tf32(float c[4],
    uint32_t a0, uint32_t a1, uint32_t a2, uint32_t a3,
    uint32_t b0, uint32_t b1)
{
    asm("mma.sync.aligned.m16n8k8.row.col.f32.tf32.tf32.f32 "
        "{%0,%1,%2,%3}, {%4,%5,%6,%7}, {%8,%9}, {%0,%1,%2,%3};"
        : "+f"(c[0]), "+f"(c[1]), "+f"(c[2]), "+f"(c[3])
        : "r"(a0), "r"(a1), "r"(a2), "r"(a3), "r"(b0), "r"(b1));
}

// ---------------- scratch ----------------
__device__ float g_proj[NN * PROJ_N];
__device__ float g_v[NN * 192];
__device__ float g_vpts[NN * 288];
__device__ float g_qb[HH * NN * 32];
__device__ float g_kb[HH * NN * 32];
__device__ float g_qkp[(size_t)NN * HH * NN]; // [i][h][j]
__device__ float g_bias[(size_t)NN * NN * HH];// [i][j][h]
__device__ float g_a[(size_t)NN * HH * NN];   // [i][h][j]
__device__ float g_optg[NN * 288];
__device__ float g_feats[NN * FEAT_N];

// ---------------- GEMM via 3xTF32 MMA: out = A @ W + bias, segmented over N ----------------
#define APITCH 20
#define BPITCH 72
__global__ __launch_bounds__(256) void gemm_mma_kernel(
    const float* __restrict__ A, int K,
    const float* __restrict__ w0, const float* __restrict__ w1,
    const float* __restrict__ w2, const float* __restrict__ w3,
    const float* __restrict__ b0, const float* __restrict__ b1,
    const float* __restrict__ b2, const float* __restrict__ b3,
    int e0, int e1, int e2, int e3,
    float* __restrict__ out, int ldo)
{
    __shared__ uint32_t Ah[64 * APITCH], Al[64 * APITCH];
    __shared__ uint32_t Bh[16 * BPITCH], Bl[16 * BPITCH];

    const int m0 = blockIdx.y * 64;
    const int n0 = blockIdx.x * 64;
    const int t = threadIdx.x;
    const int warp = t >> 5, lane = t & 31;
    const int wm = warp & 3, wn = warp >> 2;
    const int tg = lane & 3, gp = lane >> 2;

    const int brow = t >> 4;
    const int bn = (t & 15) * 4;
    const int ncol = n0 + bn;
    const float* W; int base, segN;
    if (ncol < e0)      { W = w0; base = 0;  segN = e0; }
    else if (ncol < e1) { W = w1; base = e0; segN = e1 - e0; }
    else if (ncol < e2) { W = w2; base = e1; segN = e2 - e1; }
    else                { W = w3; base = e2; segN = e3 - e2; }

    const int ar = t >> 2, ak = (t & 3) * 4;

    float acc[4][4] = {};

    for (int k0 = 0; k0 < K; k0 += 16) {
        __syncthreads();
        {
            float4 v = *(const float4*)&A[(size_t)(m0 + ar) * K + k0 + ak];
            uint4 hi, lo;
            hi.x = to_tf32(v.x); lo.x = to_tf32(v.x - __uint_as_float(hi.x));
            hi.y = to_tf32(v.y); lo.y = to_tf32(v.y - __uint_as_float(hi.y));
            hi.z = to_tf32(v.z); lo.z = to_tf32(v.z - __uint_as_float(hi.z));
            hi.w = to_tf32(v.w); lo.w = to_tf32(v.w - __uint_as_float(hi.w));
            *(uint4*)&Ah[ar * APITCH + ak] = hi;
            *(uint4*)&Al[ar * APITCH + ak] = lo;
        }
        {
            float4 v = *(const float4*)&W[(size_t)(k0 + brow) * segN + (ncol - base)];
            uint4 hi, lo;
            hi.x = to_tf32(v.x); lo.x = to_tf32(v.x - __uint_as_float(hi.x));
            hi.y = to_tf32(v.y); lo.y = to_tf32(v.y - __uint_as_float(hi.y));
            hi.z = to_tf32(v.z); lo.z = to_tf32(v.z - __uint_as_float(hi.z));
            hi.w = to_tf32(v.w); lo.w = to_tf32(v.w - __uint_as_float(hi.w));
            *(uint4*)&Bh[brow * BPITCH + bn] = hi;
            *(uint4*)&Bl[brow * BPITCH + bn] = lo;
        }
        __syncthreads();

        #pragma unroll
        for (int kk = 0; kk < 2; kk++) {
            const int k8 = kk * 8;
            const int ra = (wm * 16 + gp) * APITCH + k8 + tg;
            const int rb = (wm * 16 + gp + 8) * APITCH + k8 + tg;
            uint32_t a0h = Ah[ra],     a1h = Ah[rb];
            uint32_t a2h = Ah[ra + 4], a3h = Ah[rb + 4];
            uint32_t a0l = Al[ra],     a1l = Al[rb];
            uint32_t a2l = Al[ra + 4], a3l = Al[rb + 4];
            #pragma unroll
            for (int nt = 0; nt < 4; nt++) {
                const int nb = wn * 32 + nt * 8 + gp;
                const int i1 = (k8 + tg) * BPITCH + nb;
                const int i2 = (k8 + tg + 4) * BPITCH + nb;
                uint32_t bh0 = Bh[i1], bh1 = Bh[i2];
                uint32_t bl0 = Bl[i1], bl1 = Bl[i2];
                mma_tf32(acc[nt], a0h, a1h, a2h, a3h, bh0, bh1);
                mma_tf32(acc[nt], a0l, a1l, a2l, a3l, bh0, bh1);
                mma_tf32(acc[nt], a0h, a1h, a2h, a3h, bl0, bl1);
            }
        }
    }

    const int r0 = m0 + wm * 16 + gp;
    const int r1 = r0 + 8;
    #pragma unroll
    for (int nt = 0; nt < 4; nt++) {
        const int col = n0 + wn * 32 + nt * 8 + 2 * tg;
        const float* bp; int bb;
        if (col < e0)      { bp = b0; bb = 0; }
        else if (col < e1) { bp = b1; bb = e0; }
        else if (col < e2) { bp = b2; bb = e1; }
        else               { bp = b3; bb = e2; }
        float2 bv = *(const float2*)&bp[col - bb];
        float2 o0, o1;
        o0.x = acc[nt][0] + bv.x; o0.y = acc[nt][1] + bv.y;
        o1.x = acc[nt][2] + bv.x; o1.y = acc[nt][3] + bv.y;
        *(float2*)&out[(size_t)r0 * ldo + col] = o0;
        *(float2*)&out[(size_t)r1 * ldo + col] = o1;
    }
}

// ---------------- prep ----------------
__global__ __launch_bounds__(384) void prep_kernel(
    const float* __restrict__ rot, const float* __restrict__ trans,
    const float* __restrict__ head_w)
{
    __shared__ float s_qp3[144];
    __shared__ float s_kp3[144];

    const int n = blockIdx.x;
    const int t = threadIdx.x;
    const float* pr = &g_proj[(size_t)n * PROJ_N];

    if (t < 192) {
        int h = t >> 4, c = t & 15;
        g_kb[((size_t)h * NN + n) * 32 + c] = pr[192 + h * 32 + c];
        g_v[n * 192 + t] = pr[192 + h * 32 + 16 + c];
    }
    float r[9], tr[3];
    #pragma unroll
    for (int e = 0; e < 9; e++) r[e] = rot[n * 9 + e];
    tr[0] = trans[n * 3 + 0]; tr[1] = trans[n * 3 + 1]; tr[2] = trans[n * 3 + 2];

    if (t < 48) {
        float p0 = pr[576 + 0 * 48 + t];
        float p1 = pr[576 + 1 * 48 + t];
        float p2 = pr[576 + 2 * 48 + t];
        #pragma unroll
        for (int ii = 0; ii < 3; ii++)
            s_qp3[t * 3 + ii] = r[ii * 3 + 0] * p0 + r[ii * 3 + 1] * p1 + r[ii * 3 + 2] * p2 + tr[ii];
    }
    if (t >= 64 && t < 208) {
        int u = t - 64;
        float p0 = pr[720 + 0 * 144 + u];
        float p1 = pr[720 + 1 * 144 + u];
        float p2 = pr[720 + 2 * 144 + u];
        int h = u / 12, p = u % 12;
        #pragma unroll
        for (int ii = 0; ii < 3; ii++) {
            float o = r[ii * 3 + 0] * p0 + r[ii * 3 + 1] * p1 + r[ii * 3 + 2] * p2 + tr[ii];
            if (p < 4) s_kp3[(h * 4 + p) * 3 + ii] = o;
            else       g_vpts[n * 288 + (h * 8 + (p - 4)) * 3 + ii] = o;
        }
    }
    __syncthreads();

    {
        int h = t >> 5, e = t & 31;
        float x = head_w[h];
        float hw = ((x > 20.f) ? x : log1pf(__expf(x))) * HWF;

        float qv;
        if (e < 16)       qv = pr[h * 16 + e] * S1;
        else if (e < 28)  qv = s_qp3[h * 12 + (e - 16)] * hw;
        else if (e == 28) qv = -0.5f * hw;
        else if (e == 29) {
            float nq = 0.f;
            #pragma unroll
            for (int d = 0; d < 12; d++) { float v = s_qp3[h * 12 + d]; nq += v * v; }
            qv = -0.5f * hw * nq;
        } else qv = 0.f;
        g_qb[((size_t)h * NN + n) * 32 + e] = qv;

        if (e >= 16) {
            float kv2;
            if (e < 28)       kv2 = s_kp3[h * 12 + (e - 16)];
            else if (e == 28) {
                float nk = 0.f;
                #pragma unroll
                for (int d = 0; d < 12; d++) { float v = s_kp3[h * 12 + d]; nk += v * v; }
                kv2 = nk;
            }
            else if (e == 29) kv2 = 1.f;
            else              kv2 = 0.f;
            g_kb[((size_t)h * NN + n) * 32 + e] = kv2;
        }
    }
}

// ---------------- qkpts ----------------
__global__ __launch_bounds__(256) void qkpts_kernel(const float* __restrict__ mask)
{
    __shared__ float As[32][68];
    __shared__ float Bs[32][68];
    __shared__ float s_mi[64], s_mj[64];

    const int i0 = blockIdx.x * 64;
    const int j0 = blockIdx.y * 64;
    const int h  = blockIdx.z;
    const int t = threadIdx.x;

    #pragma unroll
    for (int r2 = 0; r2 < 2; r2++) {
        int li = t + r2 * 256;
        int row = li >> 3, c4 = (li & 7) * 4;
        float4 a = *(const float4*)&g_qb[((size_t)h * NN + i0 + row) * 32 + c4];
        As[c4 + 0][row] = a.x; As[c4 + 1][row] = a.y;
        As[c4 + 2][row] = a.z; As[c4 + 3][row] = a.w;
        float4 b = *(const float4*)&g_kb[((size_t)h * NN + j0 + row) * 32 + c4];
        Bs[c4 + 0][row] = b.x; Bs[c4 + 1][row] = b.y;
        Bs[c4 + 2][row] = b.z; Bs[c4 + 3][row] = b.w;
    }
    if (t < 64)              s_mi[t] = mask[i0 + t];
    else if (t < 128)        s_mj[t - 64] = mask[j0 + t - 64];
    __syncthreads();

    const int ty = t >> 4, tx = t & 15;
    float acc[4][4] = {};
    #pragma unroll
    for (int k = 0; k < 32; k++) {
        float4 a4 = *(const float4*)&As[k][ty * 4];
        float4 b4 = *(const float4*)&Bs[k][tx * 4];
        acc[0][0] += a4.x * b4.x; acc[0][1] += a4.x * b4.y; acc[0][2] += a4.x * b4.z; acc[0][3] += a4.x * b4.w;
        acc[1][0] += a4.y * b4.x; acc[1][1] += a4.y * b4.y; acc[1][2] += a4.y * b4.z; acc[1][3] += a4.y * b4.w;
        acc[2][0] += a4.z * b4.x; acc[2][1] += a4.z * b4.y; acc[2][2] += a4.z * b4.z; acc[2][3] += a4.z * b4.w;
        acc[3][0] += a4.w * b4.x; acc[3][1] += a4.w * b4.y; acc[3][2] += a4.w * b4.z; acc[3][3] += a4.w * b4.w;
    }
    #pragma unroll
    for (int rr = 0; rr < 4; rr++) {
        float mi = s_mi[ty * 4 + rr];
        float4 o;
        o.x = acc[rr][0] + 100000.f * (mi * s_mj[tx * 4 + 0] - 1.f);
        o.y = acc[rr][1] + 100000.f * (mi * s_mj[tx * 4 + 1] - 1.f);
        o.z = acc[rr][2] + 100000.f * (mi * s_mj[tx * 4 + 2] - 1.f);
        o.w = acc[rr][3] + 100000.f * (mi * s_mj[tx * 4 + 3] - 1.f);
        *(float4*)&g_qkp[(size_t)(i0 + ty * 4 + rr) * 9216 + h * 768 + j0 + tx * 4] = o;
    }
}

// ---------------- bias v2: smem-staged tf32 MMA GEMM ----------------
#define BT_TILES (NN * NN / 128)          // 4608
#define BS_SMEM_BYTES (128 * 132 * 4)     // 67584
__global__ __launch_bounds__(256, 2) void bias_kernel(
    const float* __restrict__ z, const float* __restrict__ w_b,
    const float* __restrict__ b_b)
{
    extern __shared__ uint32_t s_z[];     // [128][132] tf32 bits

    const int t = threadIdx.x;
    const int w = t >> 5;
    const int lane = t & 31;
    const int tg = lane & 3;
    const int gp = lane >> 2;

    uint32_t B0[16][2], B1[16][2];
    #pragma unroll
    for (int kk = 0; kk < 16; kk++) {
        int k0 = kk * 8 + tg, k1 = k0 + 4;
        B0[kk][0] = to_tf32(w_b[k0 * 12 + gp]);
        B0[kk][1] = to_tf32(w_b[k1 * 12 + gp]);
        float w10 = (gp < 4) ? w_b[k0 * 12 + 8 + gp] : 0.f;
        float w11 = (gp < 4) ? w_b[k1 * 12 + 8 + gp] : 0.f;
        B1[kk][0] = to_tf32(w10);
        B1[kk][1] = to_tf32(w11);
    }
    const int cb = 2 * tg;
    const float bb0 = b_b[cb], bb1 = b_b[cb + 1];
    const float bb8 = (cb < 4) ? b_b[8 + cb] : 0.f;
    const float bb9 = (cb < 4) ? b_b[9 + cb] : 0.f;

    const int col4 = lane * 4;
    const int rowg = w;

    for (int tile = blockIdx.x; tile < BT_TILES; tile += gridDim.x) {
        const float* zt = z + (size_t)tile * 128 * 128;
        __syncthreads();
        #pragma unroll
        for (int k = 0; k < 16; k++) {
            int row = rowg + k * 8;
            float4 v = __ldg((const float4*)(zt + row * 128 + col4));
            uint4 u;
            u.x = to_tf32(v.x); u.y = to_tf32(v.y);
            u.z = to_tf32(v.z); u.w = to_tf32(v.w);
            *(uint4*)&s_z[row * 132 + col4] = u;
        }
        __syncthreads();

        const uint32_t* sw = s_z + (w * 16) * 132;
        float c0[4] = {0.f, 0.f, 0.f, 0.f};
        float c1[4] = {0.f, 0.f, 0.f, 0.f};
        #pragma unroll
        for (int kk = 0; kk < 16; kk++) {
            int co = kk * 8 + tg;
            uint32_t a0 = sw[gp * 132 + co];
            uint32_t a1 = sw[(gp + 8) * 132 + co];
            uint32_t a2 = sw[gp * 132 + co + 4];
            uint32_t a3 = sw[(gp + 8) * 132 + co + 4];
            mma_tf32(c0, a0, a1, a2, a3, B0[kk][0], B0[kk][1]);
            mma_tf32(c1, a0, a1, a2, a3, B1[kk][0], B1[kk][1]);
        }

        float* outr = g_bias + ((size_t)tile * 128 + w * 16) * 12;
        {
            float2 o;
            o.x = SQ13 * (c0[0] + bb0); o.y = SQ13 * (c0[1] + bb1);
            *(float2*)&outr[gp * 12 + cb] = o;
            o.x = SQ13 * (c0[2] + bb0); o.y = SQ13 * (c0[3] + bb1);
            *(float2*)&outr[(gp + 8) * 12 + cb] = o;
        }
        if (cb < 4) {
            float2 o;
            o.x = SQ13 * (c1[0] + bb8); o.y = SQ13 * (c1[1] + bb9);
            *(float2*)&outr[gp * 12 + 8 + cb] = o;
            o.x = SQ13 * (c1[2] + bb8); o.y = SQ13 * (c1[3] + bb9);
            *(float2*)&outr[(gp + 8) * 12 + 8 + cb] = o;
        }
    }
}

// ---------------- smopair: softmax + o_pair fused, block = one i ----------------
#define LP 772
#define SO_SMEM_FLOATS (12 * LP + 768 + 8 * 12 * 128)
__global__ __launch_bounds__(256) void smopair_kernel(
    const float* __restrict__ z, const float* __restrict__ ss)
{
    extern __shared__ float smf[];
    float* s_l    = smf;                    // [12][LP] logits -> probs
    float* s_w    = smf + 12 * LP;          // [768]
    float* s_part = s_w + 768;              // [8][12][128]

    const int i = blockIdx.x;
    const int t = threadIdx.x;
    const int w = t >> 5, lane = t & 31;

    for (int idx = t; idx < 9216; idx += 256) {
        int j = idx / 12, h = idx - j * 12;
        s_l[h * LP + j] = g_bias[(size_t)i * 9216 + idx];
    }
    for (int idx = t; idx < 768; idx += 256)
        s_w[idx] = __expf(ss[(size_t)i * 768 + idx]) - 0.99f;
    __syncthreads();
    for (int idx = t; idx < 9216; idx += 256) {
        int h = idx / 768, j = idx - h * 768;
        s_l[h * LP + j] += g_qkp[(size_t)i * 9216 + idx];
    }
    __syncthreads();

    for (int h = w; h < 12; h += 8) {
        float* lr = &s_l[h * LP];
        float m = -1e30f;
        for (int j = lane; j < 768; j += 32) m = fmaxf(m, lr[j]);
        #pragma unroll
        for (int o = 16; o; o >>= 1) m = fmaxf(m, __shfl_xor_sync(0xffffffffu, m, o));
        float sum = 0.f;
        for (int j = lane; j < 768; j += 32) {
            float p = __expf(lr[j] - m) * s_w[j];
            lr[j] = p;
            sum += p;
        }
        #pragma unroll
        for (int o = 16; o; o >>= 1) sum += __shfl_xor_sync(0xffffffffu, sum, o);
        float inv = 1.f / sum;
        for (int j = lane; j < 768; j += 32) lr[j] *= inv;
    }
    __syncthreads();

    ull acc[6][4];
    #pragma unroll
    for (int q = 0; q < 6; q++)
        #pragma unroll
        for (int c = 0; c < 4; c++) acc[q][c] = 0ull;

    const float* zb = z + (size_t)i * 768 * 128 + lane * 4;

    for (int jb = w * 4; jb < 768; jb += 32) {
        float4 zv[4];
        #pragma unroll
        for (int u = 0; u < 4; u++)
            zv[u] = __ldg((const float4*)(zb + (size_t)(jb + u) * 128));
        #pragma unroll
        for (int u = 0; u < 4; u++) {
            const int j = jb + u;
            ull ap[6];
            #pragma unroll
            for (int q = 0; q < 6; q++)
                ap[q] = pack2(s_l[(2 * q) * LP + j], s_l[(2 * q + 1) * LP + j]);
            float zc[4] = {zv[u].x, zv[u].y, zv[u].z, zv[u].w};
            #pragma unroll
            for (int c = 0; c < 4; c++) {
                ull zz = pack2(zc[c], zc[c]);
                #pragma unroll
                for (int q = 0; q < 6; q++)
                    ffma2(acc[q][c], ap[q], zz);
            }
        }
    }

    for (int idx = t; idx < 9216; idx += 256) {
        int h = idx / 768, j = idx - h * 768;
        g_a[(size_t)i * 9216 + idx] = s_l[h * LP + j];
    }

    #pragma unroll
    for (int q = 0; q < 6; q++) {
        #pragma unroll
        for (int c = 0; c < 4; c++) {
            float2 u = unpack2(acc[q][c]);
            s_part[(w * 12 + 2 * q + 0) * 128 + lane * 4 + c] = u.x;
            s_part[(w * 12 + 2 * q + 1) * 128 + lane * 4 + c] = u.y;
        }
    }
    __syncthreads();

    for (int idx = t; idx < 1536; idx += 256) {
        int h = idx >> 7, c = idx & 127;
        float s = 0.f;
        #pragma unroll
        for (int ww = 0; ww < 8; ww++)
            s += s_part[(ww * 12 + h) * 128 + c];
        g_feats[(size_t)i * FEAT_N + 576 + h * 128 + c] = s;
    }
}

// ---------------- ov via 3xTF32 MMA: [32 i] x [768 j] @ [j x 40], grid (24,12) ----------------
// A = a-tile (32x64 per chunk), B = [v|v_pts] (64x40). Hi/lo split for fp32-grade accuracy.
__global__ __launch_bounds__(256) void ov_kernel()
{
    __shared__ uint32_t Ahh[32 * 68], All[32 * 68];
    __shared__ uint32_t Vhh[64 * 40], Vll[64 * 40];

    const int i0 = blockIdx.x * 32;
    const int h  = blockIdx.y;
    const int t = threadIdx.x;
    const int w = t >> 5, lane = t & 31;
    const int tg = lane & 3, gp = lane >> 2;

    // warp jobs: jb = w, and jb = w+8 (only w<2). job: mt = jb&1, nt = jb>>1 (nt 0..4)
    float acc0[4] = {0.f, 0.f, 0.f, 0.f};
    float acc1[4] = {0.f, 0.f, 0.f, 0.f};

    for (int j0 = 0; j0 < 768; j0 += 64) {
        __syncthreads();
        // stage a [32 rows][64 j] hi/lo
        #pragma unroll
        for (int it = 0; it < 2; it++) {
            int idx = t + it * 256;
            int row = idx >> 4, q4 = (idx & 15) * 4;
            float4 v = *(const float4*)&g_a[((size_t)(i0 + row) * 12 + h) * 768 + j0 + q4];
            uint4 hi, lo;
            hi.x = to_tf32(v.x); lo.x = to_tf32(v.x - __uint_as_float(hi.x));
            hi.y = to_tf32(v.y); lo.y = to_tf32(v.y - __uint_as_float(hi.y));
            hi.z = to_tf32(v.z); lo.z = to_tf32(v.z - __uint_as_float(hi.z));
            hi.w = to_tf32(v.w); lo.w = to_tf32(v.w - __uint_as_float(hi.w));
            *(uint4*)&Ahh[row * 68 + q4] = hi;
            *(uint4*)&All[row * 68 + q4] = lo;
        }
        // stage v|v_pts [64 j][40] hi/lo
        #pragma unroll
        for (int it = 0; it < 3; it++) {
            int idx = t + it * 256;
            if (idx < 640) {
                int jj = idx / 10, q = idx - jj * 10;
                float4 vv = (q < 4)
                    ? *(const float4*)&g_v[(j0 + jj) * 192 + h * 16 + q * 4]
                    : *(const float4*)&g_vpts[(j0 + jj) * 288 + h * 24 + (q - 4) * 4];
                uint4 hi, lo;
                hi.x = to_tf32(vv.x); lo.x = to_tf32(vv.x - __uint_as_float(hi.x));
                hi.y = to_tf32(vv.y); lo.y = to_tf32(vv.y - __uint_as_float(hi.y));
                hi.z = to_tf32(vv.z); lo.z = to_tf32(vv.z - __uint_as_float(hi.z));
                hi.w = to_tf32(vv.w); lo.w = to_tf32(vv.w - __uint_as_float(hi.w));
                *(uint4*)&Vhh[jj * 40 + q * 4] = hi;
                *(uint4*)&Vll[jj * 40 + q * 4] = lo;
            }
        }
        __syncthreads();

        // job 0: jb = w
        {
            const int mt = w & 1, nt = w >> 1;
            const int ra0 = (mt * 16 + gp) * 68;
            const int ra1 = (mt * 16 + gp + 8) * 68;
            const int nb = nt * 8 + gp;
            #pragma unroll
            for (int kk = 0; kk < 8; kk++) {
                const int k8 = kk * 8;
                uint32_t a0h = Ahh[ra0 + k8 + tg],     a1h = Ahh[ra1 + k8 + tg];
                uint32_t a2h = Ahh[ra0 + k8 + tg + 4], a3h = Ahh[ra1 + k8 + tg + 4];
                uint32_t a0l = All[ra0 + k8 + tg],     a1l = All[ra1 + k8 + tg];
                uint32_t a2l = All[ra0 + k8 + tg + 4], a3l = All[ra1 + k8 + tg + 4];
                uint32_t bh0 = Vhh[(k8 + tg) * 40 + nb], bh1 = Vhh[(k8 + tg + 4) * 40 + nb];
                uint32_t bl0 = Vll[(k8 + tg) * 40 + nb], bl1 = Vll[(k8 + tg + 4) * 40 + nb];
                mma_tf32(acc0, a0h, a1h, a2h, a3h, bh0, bh1);
                mma_tf32(acc0, a0l, a1l, a2l, a3l, bh0, bh1);
                mma_tf32(acc0, a0h, a1h, a2h, a3h, bl0, bl1);
            }
        }
        // job 1: jb = w + 8 (only warps 0,1)
        if (w < 2) {
            const int jb = w + 8;
            const int mt = jb & 1, nt = jb >> 1;   // nt = 4
            const int ra0 = (mt * 16 + gp) * 68;
            const int ra1 = (mt * 16 + gp + 8) * 68;
            const int nb = nt * 8 + gp;
            #pragma unroll
            for (int kk = 0; kk < 8; kk++) {
                const int k8 = kk * 8;
                uint32_t a0h = Ahh[ra0 + k8 + tg],     a1h = Ahh[ra1 + k8 + tg];
                uint32_t a2h = Ahh[ra0 + k8 + tg + 4], a3h = Ahh[ra1 + k8 + tg + 4];
                uint32_t a0l = All[ra0 + k8 + tg],     a1l = All[ra1 + k8 + tg];
                uint32_t a2l = All[ra0 + k8 + tg + 4], a3l = All[ra1 + k8 + tg + 4];
                uint32_t bh0 = Vhh[(k8 + tg) * 40 + nb], bh1 = Vhh[(k8 + tg + 4) * 40 + nb];
                uint32_t bl0 = Vll[(k8 + tg) * 40 + nb], bl1 = Vll[(k8 + tg + 4) * 40 + nb];
                mma_tf32(acc1, a0h, a1h, a2h, a3h, bh0, bh1);
                mma_tf32(acc1, a0l, a1l, a2l, a3l, bh0, bh1);
                mma_tf32(acc1, a0h, a1h, a2h, a3h, bl0, bl1);
            }
        }
    }

    // epilogue: write jobs
    {
        const int mt = w & 1, nt = w >> 1;
        const int r0 = i0 + mt * 16 + gp;
        const int r1 = r0 + 8;
        #pragma unroll
        for (int u = 0; u < 2; u++) {
            int e = nt * 8 + 2 * tg + u;
            float v0 = acc0[u], v1 = acc0[2 + u];
            if (e < 16) {
                g_feats[(size_t)r0 * FEAT_N + h * 16 + e] = v0;
                g_feats[(size_t)r1 * FEAT_N + h * 16 + e] = v1;
            } else {
                g_optg[r0 * 288 + h * 24 + (e - 16)] = v0;
                g_optg[r1 * 288 + h * 24 + (e - 16)] = v1;
            }
        }
    }
    if (w < 2) {
        const int jb = w + 8;
        const int mt = jb & 1, nt = jb >> 1;
        const int r0 = i0 + mt * 16 + gp;
        const int r1 = r0 + 8;
        #pragma unroll
        for (int u = 0; u < 2; u++) {
            int e = nt * 8 + 2 * tg + u;   // 32..39 -> optg 16..23
            g_optg[r0 * 288 + h * 24 + (e - 16)] = acc1[u];
            g_optg[r1 * 288 + h * 24 + (e - 16)] = acc1[2 + u];
        }
    }
}

// ---------------- optfinal ----------------
__global__ __launch_bounds__(96) void optfinal_kernel(
    const float* __restrict__ rot, const float* __restrict__ trans)
{
    const int n = blockIdx.x;
    const int hp = threadIdx.x;
    float r[9], tr[3];
    #pragma unroll
    for (int e = 0; e < 9; e++) r[e] = rot[n * 9 + e];
    tr[0] = trans[n * 3 + 0]; tr[1] = trans[n * 3 + 1]; tr[2] = trans[n * 3 + 2];

    float gx = g_optg[n * 288 + hp * 3 + 0] - tr[0];
    float gy = g_optg[n * 288 + hp * 3 + 1] - tr[1];
    float gz = g_optg[n * 288 + hp * 3 + 2] - tr[2];
    float l0 = r[0] * gx + r[3] * gy + r[6] * gz;
    float l1 = r[1] * gx + r[4] * gy + r[7] * gz;
    float l2 = r[2] * gx + r[5] * gy + r[8] * gz;

    float* f = &g_feats[(size_t)n * FEAT_N];
    f[192 + hp] = l0;
    f[288 + hp] = l1;
    f[384 + hp] = l2;
    f[480 + hp] = sqrtf(l0 * l0 + l1 * l1 + l2 * l2 + 1e-8f);
}

// ---------------- launch ----------------
extern "C" void kernel_launch(void* const* d_in, const int* in_sizes, int n_in,
                              void* d_out, int out_size)
{
    const float* s       = (const float*)d_in[0];
    const float* z       = (const float*)d_in[1];
    const float* rot     = (const float*)d_in[2];
    const float* trans   = (const float*)d_in[3];
    const float* mask    = (const float*)d_in[4];
    const float* ss      = (const float*)d_in[5];
    const float* w_q     = (const float*)d_in[6];
    const float* b_q     = (const float*)d_in[7];
    const float* w_kv    = (const float*)d_in[8];
    const float* b_kv    = (const float*)d_in[9];
    const float* w_qp    = (const float*)d_in[10];
    const float* b_qp    = (const float*)d_in[11];
    const float* w_kvp   = (const float*)d_in[12];
    const float* b_kvp   = (const float*)d_in[13];
    const float* w_b     = (const float*)d_in[14];
    const float* b_b     = (const float*)d_in[15];
    const float* head_w  = (const float*)d_in[16];
    const float* w_out   = (const float*)d_in[17];
    const float* b_out   = (const float*)d_in[18];
    float* out = (float*)d_out;

    float* proj;  cudaGetSymbolAddress((void**)&proj, g_proj);
    float* feats; cudaGetSymbolAddress((void**)&feats, g_feats);

    static bool attr_done = false;
    if (!attr_done) {
        cudaFuncSetAttribute(smopair_kernel,
                             cudaFuncAttributeMaxDynamicSharedMemorySize,
                             SO_SMEM_FLOATS * 4);
        cudaFuncSetAttribute(bias_kernel,
                             cudaFuncAttributeMaxDynamicSharedMemorySize,
                             BS_SMEM_BYTES);
        attr_done = true;
    }

    // K1: projections (768 x 1152) via 3xTF32 MMA
    gemm_mma_kernel<<<dim3(18, 12), 256>>>(
        s, CS, w_q, w_kv, w_qp, w_kvp, b_q, b_kv, b_qp, b_kvp,
        192, 576, 720, 1152, proj, PROJ_N);

    // K2: split k/v, rotate points, build logit-GEMM rows
    prep_kernel<<<NN, 384>>>(rot, trans, head_w);

    // K2b: qk+pts+mask logits as 30-dim GEMM
    qkpts_kernel<<<dim3(12, 12, 12), 256>>>(mask);

    // K3a: z-bias via smem-staged tf32 MMA (z pass 1)
    bias_kernel<<<296, 256, BS_SMEM_BYTES>>>(z, w_b, b_b);

    // K3b: fused softmax + o_pair (z pass 2)
    smopair_kernel<<<NN, 256, SO_SMEM_FLOATS * 4>>>(z, ss);

    // K4: o and o_pt via 3xTF32 MMA
    ov_kernel<<<dim3(24, 12), 256>>>();

    // K5: finalize o_pt + norms
    optfinal_kernel<<<NN, 96>>>(rot, trans);

    // K6: output GEMM (768 x 384, K=2112) via 3xTF32 MMA
    gemm_mma_kernel<<<dim3(6, 12), 256>>>(
        feats, FEAT_N, w_out, w_out, w_out, w_out, b_out, b_out, b_out, b_out,
        384, 384, 384, 384, out, CS);
}